// round 1
// baseline (speedup 1.0000x reference)
#include <cuda_runtime.h>
#include <math.h>

#define BB 64
#define TT 256
#define EE 300
#define HH 512
#define GG 1536               // 3*H
#define MM (BB*TT)            // 16384

// ---------------- scratch (static device allocations only) ----------------
__device__ __align__(256) float g_e[MM * EE];            // embedded input  [B*T, 300]
__device__ __align__(256) float g_xp[2 * MM * GG];       // input projections [dir][B*T, 1536]
__device__ __align__(256) float g_y0[MM * 2 * HH];       // layer0 output [B*T, 1024]
__device__ __align__(256) float g_h[2][2][HH][BB];       // ping-pong hidden [buf][dir][k][b]
__device__ __align__(256) float g_pooled[BB * 2 * HH];   // maxpool [B, 1024]
__device__ __align__(256) float g_hid[BB * 128];         // mlp hidden
__device__ unsigned g_bar;

// ---------------- init: zero hidden state + barrier ----------------
__global__ void init_kernel() {
    const int n = 2 * 2 * HH * BB;
    float* p = &g_h[0][0][0][0];
    for (int i = blockIdx.x * blockDim.x + threadIdx.x; i < n; i += gridDim.x * blockDim.x)
        p[i] = 0.f;
    if (blockIdx.x == 0 && threadIdx.x == 0) g_bar = 0u;
}

// ---------------- embedding gather ----------------
__global__ void embed_kernel(const int* __restrict__ x, const float* __restrict__ emb) {
    const int tok = blockIdx.x;
    const int row = x[tok];
    const float4* src = reinterpret_cast<const float4*>(emb + (size_t)row * EE);
    float4* dst = reinterpret_cast<float4*>(g_e + (size_t)tok * EE);
    for (int i = threadIdx.x; i < EE / 4; i += blockDim.x) dst[i] = src[i];
}

// ---------------- SGEMM:  C[m,n] = sum_k A[m,k]*W[n,k] + bias[n]  ----------------
// A row-major [M,K], W row-major [N,K].  grid (N/128, M/128, ndir). 256 threads.
__global__ void __launch_bounds__(256) sgemm_bias_kernel(
    const float* __restrict__ A, const float* __restrict__ W,
    const float* __restrict__ bias, float* __restrict__ C,
    int M, int N, int K)
{
    __shared__ __align__(16) float As[8][128];
    __shared__ __align__(16) float Bs[8][128];
    const int z = blockIdx.z;
    W    += (size_t)z * N * K;
    bias += (size_t)z * N;
    C    += (size_t)z * M * N;

    const int m0 = blockIdx.y * 128, n0 = blockIdx.x * 128;
    const int tid = threadIdx.x;
    const int tx = tid & 15, ty = tid >> 4;
    const int lr = tid >> 1, lq = (tid & 1) * 4;

    const float* Ag = A + (size_t)(m0 + lr) * K + lq;
    const float* Wg = W + (size_t)(n0 + lr) * K + lq;

    float acc[8][8];
#pragma unroll
    for (int i = 0; i < 8; i++)
#pragma unroll
        for (int j = 0; j < 8; j++) acc[i][j] = 0.f;

    float4 av = make_float4(0.f, 0.f, 0.f, 0.f), bv = av;
    av = *reinterpret_cast<const float4*>(Ag);     // k0=0: lq<K always (K>=8)
    bv = *reinterpret_cast<const float4*>(Wg);

    for (int k0 = 0; k0 < K; k0 += 8) {
        __syncthreads();
        As[lq + 0][lr] = av.x; As[lq + 1][lr] = av.y; As[lq + 2][lr] = av.z; As[lq + 3][lr] = av.w;
        Bs[lq + 0][lr] = bv.x; Bs[lq + 1][lr] = bv.y; Bs[lq + 2][lr] = bv.z; Bs[lq + 3][lr] = bv.w;
        __syncthreads();

        const int kn = k0 + 8;
        if (kn < K) {
            if (kn + lq < K) {   // K % 4 == 0 so a started quad is fully valid
                av = *reinterpret_cast<const float4*>(Ag + kn);
                bv = *reinterpret_cast<const float4*>(Wg + kn);
            } else {
                av = make_float4(0.f, 0.f, 0.f, 0.f);
                bv = make_float4(0.f, 0.f, 0.f, 0.f);
            }
        }

#pragma unroll
        for (int kk = 0; kk < 8; kk++) {
            float a[8], b[8];
            *reinterpret_cast<float4*>(a)     = *reinterpret_cast<const float4*>(&As[kk][ty * 8]);
            *reinterpret_cast<float4*>(a + 4) = *reinterpret_cast<const float4*>(&As[kk][ty * 8 + 4]);
            *reinterpret_cast<float4*>(b)     = *reinterpret_cast<const float4*>(&Bs[kk][tx * 8]);
            *reinterpret_cast<float4*>(b + 4) = *reinterpret_cast<const float4*>(&Bs[kk][tx * 8 + 4]);
#pragma unroll
            for (int i = 0; i < 8; i++)
#pragma unroll
                for (int j = 0; j < 8; j++)
                    acc[i][j] = fmaf(a[i], b[j], acc[i][j]);
        }
    }

#pragma unroll
    for (int i = 0; i < 8; i++) {
        const size_t m = m0 + ty * 8 + i;
#pragma unroll
        for (int j = 0; j < 8; j += 4) {
            const int n = n0 + tx * 8 + j;
            float4 c;
            c.x = acc[i][j + 0] + bias[n + 0];
            c.y = acc[i][j + 1] + bias[n + 1];
            c.z = acc[i][j + 2] + bias[n + 2];
            c.w = acc[i][j + 3] + bias[n + 3];
            *reinterpret_cast<float4*>(&C[m * N + n]) = c;
        }
    }
}

// ---------------- grid barrier (monotonic counter) ----------------
__device__ __forceinline__ void grid_barrier(unsigned& tgt, unsigned nctas) {
    __threadfence();
    __syncthreads();
    if (threadIdx.x == 0) {
        tgt += nctas;
        const unsigned t = tgt;
        const unsigned v = atomicAdd(&g_bar, 1u) + 1u;
        if (v != t) {
            while (*reinterpret_cast<volatile unsigned*>(&g_bar) < t) {}
        }
        __threadfence();
    }
    __syncthreads();
}

// ---------------- persistent BiGRU recurrence ----------------
// grid = 128 CTAs: dir = blockIdx.x>>6, k-slice (8 cols) = blockIdx.x&63. 256 threads.
// thread: kc = tid&7 (col in slice), bq = (tid>>3)&15 (batch quad), half = tid>>7 (K split).
#define WPITCH 516
#define RED_PITCH 13
__global__ void __launch_bounds__(256, 1) recur_kernel(
    const float* __restrict__ xp,    // [dir][B*T, 1536] (includes b_ih)
    const float* __restrict__ w_hh,  // [2][1536][512]
    const float* __restrict__ b_hh,  // [2][1536]
    float* __restrict__ y,           // [B*T, 1024] or nullptr
    int do_pool)
{
    extern __shared__ float sm[];
    float* Ws  = sm;                       // [24][WPITCH]
    float* hs  = sm + 24 * WPITCH;         // [512][64]  (h transposed: [k][b])
    float* red = hs + HH * BB;             // [128][RED_PITCH]

    const int cta = blockIdx.x;
    const int dir = cta >> 6;
    const int k0  = (cta & 63) * 8;
    const int tid = threadIdx.x;
    const int kc   = tid & 7;
    const int bq   = (tid >> 3) & 15;
    const int half = tid >> 7;
    const int b0 = bq * 4;

    // load W_hh slice: row jj = g*8+kc  ->  global row g*512 + k0 + kc
    {
        const float* wsrc = w_hh + (size_t)dir * GG * HH;
        for (int idx = tid; idx < 24 * 128; idx += 256) {
            const int jj = idx >> 7;
            const int kq = (idx & 127) * 4;
            const int grow = (jj >> 3) * HH + k0 + (jj & 7);
            const float4 v = *reinterpret_cast<const float4*>(&wsrc[(size_t)grow * HH + kq]);
            float* d = &Ws[jj * WPITCH + kq];
            d[0] = v.x; d[1] = v.y; d[2] = v.z; d[3] = v.w;
        }
    }
    const float br = b_hh[dir * GG + 0 * HH + k0 + kc];
    const float bz = b_hh[dir * GG + 1 * HH + k0 + kc];
    const float bn = b_hh[dir * GG + 2 * HH + k0 + kc];

    const float* wr = Ws + (0 * 8 + kc) * WPITCH + half * 256;
    const float* wz = Ws + (1 * 8 + kc) * WPITCH + half * 256;
    const float* wn = Ws + (2 * 8 + kc) * WPITCH + half * 256;

    float mx[4] = {-1e30f, -1e30f, -1e30f, -1e30f};
    unsigned bar_tgt = 0;

    for (int s = 0; s < TT; s++) {
        const int t  = dir ? (TT - 1 - s) : s;
        const int pb = s & 1;

        // stage previous hidden state (L2-coherent loads — L1 may be stale)
        {
            const float4* src = reinterpret_cast<const float4*>(&g_h[pb][dir][0][0]);
            float4* dst = reinterpret_cast<float4*>(hs);
            for (int i = tid; i < HH * BB / 4; i += 256) dst[i] = __ldcg(src + i);
        }
        __syncthreads();

        float accr[4] = {0.f, 0.f, 0.f, 0.f};
        float accz[4] = {0.f, 0.f, 0.f, 0.f};
        float accn[4] = {0.f, 0.f, 0.f, 0.f};

        const float* hb = hs + (size_t)(half * 256) * BB + b0;
#pragma unroll 4
        for (int k = 0; k < 256; k++) {
            const float4 h4 = *reinterpret_cast<const float4*>(hb + (size_t)k * BB);
            const float r = wr[k], z = wz[k], n = wn[k];
            accr[0] = fmaf(h4.x, r, accr[0]); accr[1] = fmaf(h4.y, r, accr[1]);
            accr[2] = fmaf(h4.z, r, accr[2]); accr[3] = fmaf(h4.w, r, accr[3]);
            accz[0] = fmaf(h4.x, z, accz[0]); accz[1] = fmaf(h4.y, z, accz[1]);
            accz[2] = fmaf(h4.z, z, accz[2]); accz[3] = fmaf(h4.w, z, accz[3]);
            accn[0] = fmaf(h4.x, n, accn[0]); accn[1] = fmaf(h4.y, n, accn[1]);
            accn[2] = fmaf(h4.z, n, accn[2]); accn[3] = fmaf(h4.w, n, accn[3]);
        }

        if (half) {
            float* rp = red + (size_t)(tid & 127) * RED_PITCH;
            rp[0] = accr[0]; rp[1] = accr[1]; rp[2] = accr[2]; rp[3] = accr[3];
            rp[4] = accz[0]; rp[5] = accz[1]; rp[6] = accz[2]; rp[7] = accz[3];
            rp[8] = accn[0]; rp[9] = accn[1]; rp[10] = accn[2]; rp[11] = accn[3];
        }
        __syncthreads();
        if (!half) {
            const float* rp = red + (size_t)tid * RED_PITCH;
#pragma unroll
            for (int i = 0; i < 4; i++) {
                accr[i] += rp[i]; accz[i] += rp[4 + i]; accn[i] += rp[8 + i];
            }
#pragma unroll
            for (int i = 0; i < 4; i++) {
                const int b = b0 + i;
                const size_t base = ((size_t)(dir * BB + b) * TT + t) * GG + k0 + kc;
                const float xr = xp[base];
                const float xz = xp[base + HH];
                const float xn = xp[base + 2 * HH];
                const float rg = 1.f / (1.f + expf(-(xr + accr[i] + br)));
                const float zg = 1.f / (1.f + expf(-(xz + accz[i] + bz)));
                const float ng = tanhf(xn + rg * (accn[i] + bn));
                const float hp = hs[(size_t)(k0 + kc) * BB + b];
                const float hv = (1.f - zg) * ng + zg * hp;
                __stcg(&g_h[1 - pb][dir][k0 + kc][b], hv);
                if (y) y[((size_t)b * TT + t) * (2 * HH) + dir * HH + k0 + kc] = hv;
                if (do_pool) mx[i] = fmaxf(mx[i], hv);
            }
        }
        grid_barrier(bar_tgt, gridDim.x);
    }

    if (do_pool && !half) {
#pragma unroll
        for (int i = 0; i < 4; i++)
            g_pooled[(size_t)(b0 + i) * (2 * HH) + dir * HH + k0 + kc] = mx[i];
    }
}

// ---------------- classifier head ----------------
__global__ void mlp1_kernel(const float* __restrict__ w1, const float* __restrict__ b1) {
    const int warp = (blockIdx.x * blockDim.x + threadIdx.x) >> 5;
    const int lane = threadIdx.x & 31;
    if (warp >= BB * 128) return;
    const int b = warp >> 7, j = warp & 127;
    const float* p = g_pooled + (size_t)b * 2 * HH;
    const float* w = w1 + (size_t)j * 2 * HH;
    float s = 0.f;
    for (int k = lane; k < 2 * HH; k += 32) s = fmaf(p[k], w[k], s);
#pragma unroll
    for (int o = 16; o; o >>= 1) s += __shfl_xor_sync(0xffffffffu, s, o);
    if (lane == 0) g_hid[b * 128 + j] = fmaxf(s + b1[j], 0.f);
}

__global__ void mlp2_kernel(const float* __restrict__ w2, const float* __restrict__ b2,
                            float* __restrict__ out) {
    const int t = threadIdx.x;
    if (t < BB * 2) {
        const int b = t >> 1, c = t & 1;
        float s = b2[c];
        const float* h = g_hid + b * 128;
        const float* w = w2 + c * 128;
        for (int k = 0; k < 128; k++) s = fmaf(h[k], w[k], s);
        out[t] = s;
    }
}

// ---------------- launch ----------------
extern "C" void kernel_launch(void* const* d_in, const int* in_sizes, int n_in,
                              void* d_out, int out_size) {
    const int*   x    = (const int*)d_in[0];
    const float* emb  = (const float*)d_in[1];
    const float* wih0 = (const float*)d_in[2];
    const float* whh0 = (const float*)d_in[3];
    const float* bih0 = (const float*)d_in[4];
    const float* bhh0 = (const float*)d_in[5];
    const float* wih1 = (const float*)d_in[6];
    const float* whh1 = (const float*)d_in[7];
    const float* bih1 = (const float*)d_in[8];
    const float* bhh1 = (const float*)d_in[9];
    const float* w1   = (const float*)d_in[10];
    const float* b1   = (const float*)d_in[11];
    const float* w2   = (const float*)d_in[12];
    const float* b2   = (const float*)d_in[13];

    float *e_p = nullptr, *xp_p = nullptr, *y0_p = nullptr;
    cudaGetSymbolAddress((void**)&e_p,  g_e);
    cudaGetSymbolAddress((void**)&xp_p, g_xp);
    cudaGetSymbolAddress((void**)&y0_p, g_y0);

    const size_t smem = (size_t)(24 * WPITCH + HH * BB + 128 * RED_PITCH) * sizeof(float);
    cudaFuncSetAttribute(recur_kernel, cudaFuncAttributeMaxDynamicSharedMemorySize, (int)smem);

    // layer 0
    init_kernel<<<64, 256>>>();
    embed_kernel<<<MM, 128>>>(x, emb);
    sgemm_bias_kernel<<<dim3(GG / 128, MM / 128, 2), 256>>>(e_p, wih0, bih0, xp_p, MM, GG, EE);
    recur_kernel<<<128, 256, smem>>>(xp_p, whh0, bhh0, y0_p, 0);
    // layer 1
    sgemm_bias_kernel<<<dim3(GG / 128, MM / 128, 2), 256>>>(y0_p, wih1, bih1, xp_p, MM, GG, 2 * HH);
    init_kernel<<<64, 256>>>();
    recur_kernel<<<128, 256, smem>>>(xp_p, whh1, bhh1, nullptr, 1);
    // head
    mlp1_kernel<<<(BB * 128 * 32) / 256, 256>>>(w1, b1);
    mlp2_kernel<<<1, 128>>>(w2, b2, (float*)d_out);
}

// round 2
// speedup vs baseline: 1.2218x; 1.2218x over previous
#include <cuda_runtime.h>
#include <cuda_bf16.h>
#include <math.h>

#define BB 64
#define TT 256
#define EE 300
#define HH 512
#define GG 1536               // 3*H
#define MM (BB*TT)            // 16384

// ---------------- scratch (static device allocations only) ----------------
__device__ __align__(256) float g_e[MM * EE];            // embedded input  [B*T, 300]
__device__ __align__(256) float g_xp[2 * MM * GG];       // input projections [dir][B*T, 1536]
__device__ __align__(256) float g_y0[MM * 2 * HH];       // layer0 output [B*T, 1024]
__device__ __align__(256) float g_h[2][2][HH][BB];       // ping-pong hidden [buf][dir][k][b]
__device__ __align__(256) float g_pooled[BB * 2 * HH];   // maxpool [B, 1024]
__device__ __align__(256) float g_hid[BB * 128];         // mlp hidden
__device__ __align__(256) __nv_bfloat16 g_a3[MM * 3 * 1024];        // split A [M, 3*Kp]
__device__ __align__(256) __nv_bfloat16 g_w3[2 * GG * 3 * 1024];    // split W [2N, 3*Kp]
__device__ unsigned g_bar;

// ---------------- init: zero hidden state + barrier ----------------
__global__ void init_kernel() {
    const int n = 2 * 2 * HH * BB;
    float* p = &g_h[0][0][0][0];
    for (int i = blockIdx.x * blockDim.x + threadIdx.x; i < n; i += gridDim.x * blockDim.x)
        p[i] = 0.f;
    if (blockIdx.x == 0 && threadIdx.x == 0) g_bar = 0u;
}

// ---------------- embedding gather ----------------
__global__ void embed_kernel(const int* __restrict__ x, const float* __restrict__ emb) {
    const int tok = blockIdx.x;
    const int row = x[tok];
    const float4* src = reinterpret_cast<const float4*>(emb + (size_t)row * EE);
    float4* dst = reinterpret_cast<float4*>(g_e + (size_t)tok * EE);
    for (int i = threadIdx.x; i < EE / 4; i += blockDim.x) dst[i] = src[i];
}

// ---------------- bf16 split conversion ----------------
// mode 0 (A): slabs = [hi | hi | lo];  mode 1 (W): slabs = [hi | lo | hi]
__global__ void conv_split_kernel(const float* __restrict__ src, __nv_bfloat16* __restrict__ dst,
                                  int rows, int Ksrc, int Kp, int mode) {
    const long i = (long)blockIdx.x * blockDim.x + threadIdx.x;   // pair index
    const long total = (long)rows * (Kp / 2);
    if (i >= total) return;
    const int m  = (int)(i / (Kp / 2));
    const int k0 = (int)(i % (Kp / 2)) * 2;
    const float v0 = (k0     < Ksrc) ? src[(size_t)m * Ksrc + k0]     : 0.f;
    const float v1 = (k0 + 1 < Ksrc) ? src[(size_t)m * Ksrc + k0 + 1] : 0.f;
    const __nv_bfloat16 h0 = __float2bfloat16(v0), h1 = __float2bfloat16(v1);
    const __nv_bfloat16 l0 = __float2bfloat16(v0 - __bfloat162float(h0));
    const __nv_bfloat16 l1 = __float2bfloat16(v1 - __bfloat162float(h1));
    const __nv_bfloat162 hh = __halves2bfloat162(h0, h1);
    const __nv_bfloat162 ll = __halves2bfloat162(l0, l1);
    __nv_bfloat162* d = reinterpret_cast<__nv_bfloat162*>(dst + (size_t)m * 3 * Kp);
    const int p = k0 >> 1, s = Kp >> 1;
    if (mode == 0) { d[p] = hh; d[p + s] = hh; d[p + 2 * s] = ll; }
    else           { d[p] = hh; d[p + s] = ll; d[p + 2 * s] = hh; }
}

// ---------------- bf16 tensor-core GEMM with fused bias ----------------
// C[z][m,n] = sum_k A[m,k]*W[z][n,k] + bias[z][n].  128x128x32 tiles, 8 warps.
#define PKH 40
__global__ void __launch_bounds__(256, 2) bgemm_kernel(
    const __nv_bfloat16* __restrict__ A,   // [M, K3]
    const __nv_bfloat16* __restrict__ W,   // [2][N, K3]
    const float* __restrict__ bias,        // [2][N]
    float* __restrict__ C,                 // [2][M, N]
    int M, int N, int K3)
{
    __shared__ __align__(16) __nv_bfloat16 As[2][128 * PKH];
    __shared__ __align__(16) __nv_bfloat16 Bs[2][128 * PKH];

    const int z = blockIdx.z;
    W    += (size_t)z * N * K3;
    bias += (size_t)z * N;
    C    += (size_t)z * M * N;

    const int m0 = blockIdx.y * 128, n0 = blockIdx.x * 128;
    const int tid = threadIdx.x;
    const int warp = tid >> 5, lane = tid & 31;
    const int wm = warp >> 2, wn = warp & 3;

    float c[4][4][4];
#pragma unroll
    for (int mi = 0; mi < 4; mi++)
#pragma unroll
        for (int ni = 0; ni < 4; ni++)
#pragma unroll
            for (int q = 0; q < 4; q++) c[mi][ni][q] = 0.f;

    const int lrow = tid >> 2;          // 0..63
    const int lcol = (tid & 3) * 8;     // halves

    // preload tile 0 into buffer 0
    {
        const uint4 a0 = *reinterpret_cast<const uint4*>(A + (size_t)(m0 + lrow) * K3 + lcol);
        const uint4 a1 = *reinterpret_cast<const uint4*>(A + (size_t)(m0 + lrow + 64) * K3 + lcol);
        const uint4 b0 = *reinterpret_cast<const uint4*>(W + (size_t)(n0 + lrow) * K3 + lcol);
        const uint4 b1 = *reinterpret_cast<const uint4*>(W + (size_t)(n0 + lrow + 64) * K3 + lcol);
        *reinterpret_cast<uint4*>(&As[0][lrow * PKH + lcol]) = a0;
        *reinterpret_cast<uint4*>(&As[0][(lrow + 64) * PKH + lcol]) = a1;
        *reinterpret_cast<uint4*>(&Bs[0][lrow * PKH + lcol]) = b0;
        *reinterpret_cast<uint4*>(&Bs[0][(lrow + 64) * PKH + lcol]) = b1;
    }
    __syncthreads();

    const int nk = K3 / 32;
    uint4 pa0, pa1, pb0, pb1;

    for (int kt = 0; kt < nk; kt++) {
        const int cur = kt & 1;
        if (kt + 1 < nk) {
            const int kg = (kt + 1) * 32 + lcol;
            pa0 = *reinterpret_cast<const uint4*>(A + (size_t)(m0 + lrow) * K3 + kg);
            pa1 = *reinterpret_cast<const uint4*>(A + (size_t)(m0 + lrow + 64) * K3 + kg);
            pb0 = *reinterpret_cast<const uint4*>(W + (size_t)(n0 + lrow) * K3 + kg);
            pb1 = *reinterpret_cast<const uint4*>(W + (size_t)(n0 + lrow + 64) * K3 + kg);
        }

        const unsigned abase = (unsigned)__cvta_generic_to_shared(&As[cur][0]);
        const unsigned bbase = (unsigned)__cvta_generic_to_shared(&Bs[cur][0]);

#pragma unroll
        for (int kk = 0; kk < 32; kk += 16) {
            unsigned a[4][4], b[4][2];
#pragma unroll
            for (int mi = 0; mi < 4; mi++) {
                const unsigned ad = abase +
                    (((wm * 64 + mi * 16 + (lane & 15)) * PKH + kk + (lane >> 4) * 8) << 1);
                asm volatile("ldmatrix.sync.aligned.m8n8.x4.shared.b16 {%0,%1,%2,%3}, [%4];"
                    : "=r"(a[mi][0]), "=r"(a[mi][1]), "=r"(a[mi][2]), "=r"(a[mi][3]) : "r"(ad));
            }
#pragma unroll
            for (int nj = 0; nj < 2; nj++) {
                const int g = lane >> 3, rr = lane & 7;
                const unsigned bd = bbase +
                    (((wn * 32 + nj * 16 + (g >> 1) * 8 + rr) * PKH + kk + (g & 1) * 8) << 1);
                asm volatile("ldmatrix.sync.aligned.m8n8.x4.shared.b16 {%0,%1,%2,%3}, [%4];"
                    : "=r"(b[nj * 2][0]), "=r"(b[nj * 2][1]),
                      "=r"(b[nj * 2 + 1][0]), "=r"(b[nj * 2 + 1][1]) : "r"(bd));
            }
#pragma unroll
            for (int mi = 0; mi < 4; mi++)
#pragma unroll
                for (int ni = 0; ni < 4; ni++)
                    asm volatile(
                        "mma.sync.aligned.m16n8k16.row.col.f32.bf16.bf16.f32 "
                        "{%0,%1,%2,%3}, {%4,%5,%6,%7}, {%8,%9}, {%0,%1,%2,%3};"
                        : "+f"(c[mi][ni][0]), "+f"(c[mi][ni][1]),
                          "+f"(c[mi][ni][2]), "+f"(c[mi][ni][3])
                        : "r"(a[mi][0]), "r"(a[mi][1]), "r"(a[mi][2]), "r"(a[mi][3]),
                          "r"(b[ni][0]), "r"(b[ni][1]));
        }

        if (kt + 1 < nk) {
            const int nxt = cur ^ 1;
            *reinterpret_cast<uint4*>(&As[nxt][lrow * PKH + lcol]) = pa0;
            *reinterpret_cast<uint4*>(&As[nxt][(lrow + 64) * PKH + lcol]) = pa1;
            *reinterpret_cast<uint4*>(&Bs[nxt][lrow * PKH + lcol]) = pb0;
            *reinterpret_cast<uint4*>(&Bs[nxt][(lrow + 64) * PKH + lcol]) = pb1;
            __syncthreads();
        }
    }

#pragma unroll
    for (int mi = 0; mi < 4; mi++) {
        const int row = m0 + wm * 64 + mi * 16 + (lane >> 2);
#pragma unroll
        for (int ni = 0; ni < 4; ni++) {
            const int col = n0 + wn * 32 + ni * 8 + (lane & 3) * 2;
            const float bx = bias[col], by = bias[col + 1];
            float2 v0 = make_float2(c[mi][ni][0] + bx, c[mi][ni][1] + by);
            float2 v1 = make_float2(c[mi][ni][2] + bx, c[mi][ni][3] + by);
            *reinterpret_cast<float2*>(&C[(size_t)row * N + col]) = v0;
            *reinterpret_cast<float2*>(&C[(size_t)(row + 8) * N + col]) = v1;
        }
    }
}

// ---------------- grid barrier (monotonic counter) ----------------
__device__ __forceinline__ void grid_barrier(unsigned& tgt, unsigned nctas) {
    __threadfence();
    __syncthreads();
    if (threadIdx.x == 0) {
        tgt += nctas;
        const unsigned t = tgt;
        const unsigned v = atomicAdd(&g_bar, 1u) + 1u;
        if (v != t) {
            while (*reinterpret_cast<volatile unsigned*>(&g_bar) < t) {}
        }
        __threadfence();
    }
    __syncthreads();
}

// ---------------- persistent BiGRU recurrence ----------------
#define WPITCH 516
#define RED_PITCH 13
__global__ void __launch_bounds__(256, 1) recur_kernel(
    const float* __restrict__ xp,    // [dir][B*T, 1536] (includes b_ih)
    const float* __restrict__ w_hh,  // [2][1536][512]
    const float* __restrict__ b_hh,  // [2][1536]
    float* __restrict__ y,           // [B*T, 1024] or nullptr
    int do_pool)
{
    extern __shared__ float sm[];
    float* Ws  = sm;                       // [24][WPITCH]
    float* hs  = sm + 24 * WPITCH;         // [512][64]  (h transposed: [k][b])
    float* red = hs + HH * BB;             // [128][RED_PITCH]

    const int cta = blockIdx.x;
    const int dir = cta >> 6;
    const int k0  = (cta & 63) * 8;
    const int tid = threadIdx.x;
    const int kc   = tid & 7;
    const int bq   = (tid >> 3) & 15;
    const int half = tid >> 7;
    const int b0 = bq * 4;

    {
        const float* wsrc = w_hh + (size_t)dir * GG * HH;
        for (int idx = tid; idx < 24 * 128; idx += 256) {
            const int jj = idx >> 7;
            const int kq = (idx & 127) * 4;
            const int grow = (jj >> 3) * HH + k0 + (jj & 7);
            const float4 v = *reinterpret_cast<const float4*>(&wsrc[(size_t)grow * HH + kq]);
            float* d = &Ws[jj * WPITCH + kq];
            d[0] = v.x; d[1] = v.y; d[2] = v.z; d[3] = v.w;
        }
    }
    const float br = b_hh[dir * GG + 0 * HH + k0 + kc];
    const float bz = b_hh[dir * GG + 1 * HH + k0 + kc];
    const float bn = b_hh[dir * GG + 2 * HH + k0 + kc];

    const float* wr = Ws + (0 * 8 + kc) * WPITCH + half * 256;
    const float* wz = Ws + (1 * 8 + kc) * WPITCH + half * 256;
    const float* wn = Ws + (2 * 8 + kc) * WPITCH + half * 256;

    float mx[4] = {-1e30f, -1e30f, -1e30f, -1e30f};
    unsigned bar_tgt = 0;

    for (int s = 0; s < TT; s++) {
        const int t  = dir ? (TT - 1 - s) : s;
        const int pb = s & 1;

        {
            const float4* src = reinterpret_cast<const float4*>(&g_h[pb][dir][0][0]);
            float4* dst = reinterpret_cast<float4*>(hs);
            for (int i = tid; i < HH * BB / 4; i += 256) dst[i] = __ldcg(src + i);
        }
        __syncthreads();

        float accr[4] = {0.f, 0.f, 0.f, 0.f};
        float accz[4] = {0.f, 0.f, 0.f, 0.f};
        float accn[4] = {0.f, 0.f, 0.f, 0.f};

        const float* hb = hs + (size_t)(half * 256) * BB + b0;
#pragma unroll 4
        for (int k = 0; k < 256; k++) {
            const float4 h4 = *reinterpret_cast<const float4*>(hb + (size_t)k * BB);
            const float r = wr[k], z = wz[k], n = wn[k];
            accr[0] = fmaf(h4.x, r, accr[0]); accr[1] = fmaf(h4.y, r, accr[1]);
            accr[2] = fmaf(h4.z, r, accr[2]); accr[3] = fmaf(h4.w, r, accr[3]);
            accz[0] = fmaf(h4.x, z, accz[0]); accz[1] = fmaf(h4.y, z, accz[1]);
            accz[2] = fmaf(h4.z, z, accz[2]); accz[3] = fmaf(h4.w, z, accz[3]);
            accn[0] = fmaf(h4.x, n, accn[0]); accn[1] = fmaf(h4.y, n, accn[1]);
            accn[2] = fmaf(h4.z, n, accn[2]); accn[3] = fmaf(h4.w, n, accn[3]);
        }

        if (half) {
            float* rp = red + (size_t)(tid & 127) * RED_PITCH;
            rp[0] = accr[0]; rp[1] = accr[1]; rp[2] = accr[2]; rp[3] = accr[3];
            rp[4] = accz[0]; rp[5] = accz[1]; rp[6] = accz[2]; rp[7] = accz[3];
            rp[8] = accn[0]; rp[9] = accn[1]; rp[10] = accn[2]; rp[11] = accn[3];
        }
        __syncthreads();
        if (!half) {
            const float* rp = red + (size_t)tid * RED_PITCH;
#pragma unroll
            for (int i = 0; i < 4; i++) {
                accr[i] += rp[i]; accz[i] += rp[4 + i]; accn[i] += rp[8 + i];
            }
#pragma unroll
            for (int i = 0; i < 4; i++) {
                const int b = b0 + i;
                const size_t base = ((size_t)(dir * BB + b) * TT + t) * GG + k0 + kc;
                const float xr = xp[base];
                const float xz = xp[base + HH];
                const float xn = xp[base + 2 * HH];
                const float rg = 1.f / (1.f + expf(-(xr + accr[i] + br)));
                const float zg = 1.f / (1.f + expf(-(xz + accz[i] + bz)));
                const float ng = tanhf(xn + rg * (accn[i] + bn));
                const float hp = hs[(size_t)(k0 + kc) * BB + b];
                const float hv = (1.f - zg) * ng + zg * hp;
                __stcg(&g_h[1 - pb][dir][k0 + kc][b], hv);
                if (y) y[((size_t)b * TT + t) * (2 * HH) + dir * HH + k0 + kc] = hv;
                if (do_pool) mx[i] = fmaxf(mx[i], hv);
            }
        }
        grid_barrier(bar_tgt, gridDim.x);
    }

    if (do_pool && !half) {
#pragma unroll
        for (int i = 0; i < 4; i++)
            g_pooled[(size_t)(b0 + i) * (2 * HH) + dir * HH + k0 + kc] = mx[i];
    }
}

// ---------------- classifier head ----------------
__global__ void mlp1_kernel(const float* __restrict__ w1, const float* __restrict__ b1) {
    const int warp = (blockIdx.x * blockDim.x + threadIdx.x) >> 5;
    const int lane = threadIdx.x & 31;
    if (warp >= BB * 128) return;
    const int b = warp >> 7, j = warp & 127;
    const float* p = g_pooled + (size_t)b * 2 * HH;
    const float* w = w1 + (size_t)j * 2 * HH;
    float s = 0.f;
    for (int k = lane; k < 2 * HH; k += 32) s = fmaf(p[k], w[k], s);
#pragma unroll
    for (int o = 16; o; o >>= 1) s += __shfl_xor_sync(0xffffffffu, s, o);
    if (lane == 0) g_hid[b * 128 + j] = fmaxf(s + b1[j], 0.f);
}

__global__ void mlp2_kernel(const float* __restrict__ w2, const float* __restrict__ b2,
                            float* __restrict__ out) {
    const int t = threadIdx.x;
    if (t < BB * 2) {
        const int b = t >> 1, c = t & 1;
        float s = b2[c];
        const float* h = g_hid + b * 128;
        const float* w = w2 + c * 128;
        for (int k = 0; k < 128; k++) s = fmaf(h[k], w[k], s);
        out[t] = s;
    }
}

// ---------------- launch ----------------
extern "C" void kernel_launch(void* const* d_in, const int* in_sizes, int n_in,
                              void* d_out, int out_size) {
    const int*   x    = (const int*)d_in[0];
    const float* emb  = (const float*)d_in[1];
    const float* wih0 = (const float*)d_in[2];
    const float* whh0 = (const float*)d_in[3];
    const float* bih0 = (const float*)d_in[4];
    const float* bhh0 = (const float*)d_in[5];
    const float* wih1 = (const float*)d_in[6];
    const float* whh1 = (const float*)d_in[7];
    const float* bih1 = (const float*)d_in[8];
    const float* bhh1 = (const float*)d_in[9];
    const float* w1   = (const float*)d_in[10];
    const float* b1   = (const float*)d_in[11];
    const float* w2   = (const float*)d_in[12];
    const float* b2   = (const float*)d_in[13];

    float *e_p = nullptr, *xp_p = nullptr, *y0_p = nullptr;
    __nv_bfloat16 *a3_p = nullptr, *w3_p = nullptr;
    cudaGetSymbolAddress((void**)&e_p,  g_e);
    cudaGetSymbolAddress((void**)&xp_p, g_xp);
    cudaGetSymbolAddress((void**)&y0_p, g_y0);
    cudaGetSymbolAddress((void**)&a3_p, g_a3);
    cudaGetSymbolAddress((void**)&w3_p, g_w3);

    const size_t smem = (size_t)(24 * WPITCH + HH * BB + 128 * RED_PITCH) * sizeof(float);
    cudaFuncSetAttribute(recur_kernel, cudaFuncAttributeMaxDynamicSharedMemorySize, (int)smem);

    // ---- layer 0 ----
    init_kernel<<<64, 256>>>();
    embed_kernel<<<MM, 128>>>(x, emb);
    {   // split-convert A (mode 0) and W (mode 1), Kp=320
        const long pa = (long)MM * (320 / 2);
        conv_split_kernel<<<(unsigned)((pa + 255) / 256), 256>>>(e_p, a3_p, MM, EE, 320, 0);
        const long pw = (long)(2 * GG) * (320 / 2);
        conv_split_kernel<<<(unsigned)((pw + 255) / 256), 256>>>(wih0, w3_p, 2 * GG, EE, 320, 1);
    }
    bgemm_kernel<<<dim3(GG / 128, MM / 128, 2), 256>>>(a3_p, w3_p, bih0, xp_p, MM, GG, 960);
    recur_kernel<<<128, 256, smem>>>(xp_p, whh0, bhh0, y0_p, 0);

    // ---- layer 1 ----
    {   // Kp=1024
        const long pa = (long)MM * (1024 / 2);
        conv_split_kernel<<<(unsigned)((pa + 255) / 256), 256>>>(y0_p, a3_p, MM, 2 * HH, 1024, 0);
        const long pw = (long)(2 * GG) * (1024 / 2);
        conv_split_kernel<<<(unsigned)((pw + 255) / 256), 256>>>(wih1, w3_p, 2 * GG, 2 * HH, 1024, 1);
    }
    bgemm_kernel<<<dim3(GG / 128, MM / 128, 2), 256>>>(a3_p, w3_p, bih1, xp_p, MM, GG, 3072);
    init_kernel<<<64, 256>>>();
    recur_kernel<<<128, 256, smem>>>(xp_p, whh1, bhh1, nullptr, 1);

    // ---- head ----
    mlp1_kernel<<<(BB * 128 * 32) / 256, 256>>>(w1, b1);
    mlp2_kernel<<<1, 128>>>(w2, b2, (float*)d_out);
}

// round 3
// speedup vs baseline: 2.2185x; 1.8158x over previous
#include <cuda_runtime.h>
#include <cuda_bf16.h>
#include <math.h>

#define BB 64
#define TT 256
#define EE 300
#define HH 512
#define GG 1536               // 3*H
#define MM (BB*TT)            // 16384

// ---------------- scratch (static device allocations only) ----------------
__device__ __align__(256) float g_e[MM * EE];            // embedded input  [B*T, 300]
__device__ __align__(256) float g_xp[2 * MM * GG];       // input projections [dir][B*T, 1536]
__device__ __align__(256) float g_y0[MM * 2 * HH];       // layer0 output [B*T, 1024]
__device__ __align__(256) __nv_bfloat16 g_hA[2][2][BB][1024]; // h split [buf][dir][b][hi 0..511 | lo 512..1023]
__device__ __align__(256) float g_pooled[BB * 2 * HH];   // maxpool [B, 1024]
__device__ __align__(256) float g_hid[BB * 128];         // mlp hidden
__device__ __align__(256) __nv_bfloat16 g_a3[MM * 3 * 1024];        // split A [M, 3*Kp]
__device__ __align__(256) __nv_bfloat16 g_w3[2 * GG * 3 * 1024];    // split W [2N, 3*Kp]
__device__ unsigned g_bar;

// ---------------- init: zero hidden split buffers + barrier ----------------
__global__ void init_kernel() {
    const int n = 2 * 2 * BB * 1024 / 2;   // as uint count
    unsigned* p = reinterpret_cast<unsigned*>(&g_hA[0][0][0][0]);
    for (int i = blockIdx.x * blockDim.x + threadIdx.x; i < n; i += gridDim.x * blockDim.x)
        p[i] = 0u;
    if (blockIdx.x == 0 && threadIdx.x == 0) g_bar = 0u;
}

// ---------------- embedding gather ----------------
__global__ void embed_kernel(const int* __restrict__ x, const float* __restrict__ emb) {
    const int tok = blockIdx.x;
    const int row = x[tok];
    const float4* src = reinterpret_cast<const float4*>(emb + (size_t)row * EE);
    float4* dst = reinterpret_cast<float4*>(g_e + (size_t)tok * EE);
    for (int i = threadIdx.x; i < EE / 4; i += blockDim.x) dst[i] = src[i];
}

// ---------------- bf16 split conversion ----------------
// mode 0 (A): slabs = [hi | hi | lo];  mode 1 (W): slabs = [hi | lo | hi]
__global__ void conv_split_kernel(const float* __restrict__ src, __nv_bfloat16* __restrict__ dst,
                                  int rows, int Ksrc, int Kp, int mode) {
    const long i = (long)blockIdx.x * blockDim.x + threadIdx.x;   // pair index
    const long total = (long)rows * (Kp / 2);
    if (i >= total) return;
    const int m  = (int)(i / (Kp / 2));
    const int k0 = (int)(i % (Kp / 2)) * 2;
    const float v0 = (k0     < Ksrc) ? src[(size_t)m * Ksrc + k0]     : 0.f;
    const float v1 = (k0 + 1 < Ksrc) ? src[(size_t)m * Ksrc + k0 + 1] : 0.f;
    const __nv_bfloat16 h0 = __float2bfloat16(v0), h1 = __float2bfloat16(v1);
    const __nv_bfloat16 l0 = __float2bfloat16(v0 - __bfloat162float(h0));
    const __nv_bfloat16 l1 = __float2bfloat16(v1 - __bfloat162float(h1));
    const __nv_bfloat162 hh = __halves2bfloat162(h0, h1);
    const __nv_bfloat162 ll = __halves2bfloat162(l0, l1);
    __nv_bfloat162* d = reinterpret_cast<__nv_bfloat162*>(dst + (size_t)m * 3 * Kp);
    const int p = k0 >> 1, s = Kp >> 1;
    if (mode == 0) { d[p] = hh; d[p + s] = hh; d[p + 2 * s] = ll; }
    else           { d[p] = hh; d[p + s] = ll; d[p + 2 * s] = hh; }
}

// ---------------- bf16 tensor-core GEMM with fused bias ----------------
#define PKH 40
__global__ void __launch_bounds__(256, 2) bgemm_kernel(
    const __nv_bfloat16* __restrict__ A,   // [M, K3]
    const __nv_bfloat16* __restrict__ W,   // [2][N, K3]
    const float* __restrict__ bias,        // [2][N]
    float* __restrict__ C,                 // [2][M, N]
    int M, int N, int K3)
{
    __shared__ __align__(16) __nv_bfloat16 As[2][128 * PKH];
    __shared__ __align__(16) __nv_bfloat16 Bs[2][128 * PKH];

    const int z = blockIdx.z;
    W    += (size_t)z * N * K3;
    bias += (size_t)z * N;
    C    += (size_t)z * M * N;

    const int m0 = blockIdx.y * 128, n0 = blockIdx.x * 128;
    const int tid = threadIdx.x;
    const int warp = tid >> 5, lane = tid & 31;
    const int wm = warp >> 2, wn = warp & 3;

    float c[4][4][4];
#pragma unroll
    for (int mi = 0; mi < 4; mi++)
#pragma unroll
        for (int ni = 0; ni < 4; ni++)
#pragma unroll
            for (int q = 0; q < 4; q++) c[mi][ni][q] = 0.f;

    const int lrow = tid >> 2;
    const int lcol = (tid & 3) * 8;

    {
        const uint4 a0 = *reinterpret_cast<const uint4*>(A + (size_t)(m0 + lrow) * K3 + lcol);
        const uint4 a1 = *reinterpret_cast<const uint4*>(A + (size_t)(m0 + lrow + 64) * K3 + lcol);
        const uint4 b0 = *reinterpret_cast<const uint4*>(W + (size_t)(n0 + lrow) * K3 + lcol);
        const uint4 b1 = *reinterpret_cast<const uint4*>(W + (size_t)(n0 + lrow + 64) * K3 + lcol);
        *reinterpret_cast<uint4*>(&As[0][lrow * PKH + lcol]) = a0;
        *reinterpret_cast<uint4*>(&As[0][(lrow + 64) * PKH + lcol]) = a1;
        *reinterpret_cast<uint4*>(&Bs[0][lrow * PKH + lcol]) = b0;
        *reinterpret_cast<uint4*>(&Bs[0][(lrow + 64) * PKH + lcol]) = b1;
    }
    __syncthreads();

    const int nk = K3 / 32;
    uint4 pa0, pa1, pb0, pb1;

    for (int kt = 0; kt < nk; kt++) {
        const int cur = kt & 1;
        if (kt + 1 < nk) {
            const int kg = (kt + 1) * 32 + lcol;
            pa0 = *reinterpret_cast<const uint4*>(A + (size_t)(m0 + lrow) * K3 + kg);
            pa1 = *reinterpret_cast<const uint4*>(A + (size_t)(m0 + lrow + 64) * K3 + kg);
            pb0 = *reinterpret_cast<const uint4*>(W + (size_t)(n0 + lrow) * K3 + kg);
            pb1 = *reinterpret_cast<const uint4*>(W + (size_t)(n0 + lrow + 64) * K3 + kg);
        }

        const unsigned abase = (unsigned)__cvta_generic_to_shared(&As[cur][0]);
        const unsigned bbase = (unsigned)__cvta_generic_to_shared(&Bs[cur][0]);

#pragma unroll
        for (int kk = 0; kk < 32; kk += 16) {
            unsigned a[4][4], b[4][2];
#pragma unroll
            for (int mi = 0; mi < 4; mi++) {
                const unsigned ad = abase +
                    (((wm * 64 + mi * 16 + (lane & 15)) * PKH + kk + (lane >> 4) * 8) << 1);
                asm volatile("ldmatrix.sync.aligned.m8n8.x4.shared.b16 {%0,%1,%2,%3}, [%4];"
                    : "=r"(a[mi][0]), "=r"(a[mi][1]), "=r"(a[mi][2]), "=r"(a[mi][3]) : "r"(ad));
            }
#pragma unroll
            for (int nj = 0; nj < 2; nj++) {
                const int g = lane >> 3, rr = lane & 7;
                const unsigned bd = bbase +
                    (((wn * 32 + nj * 16 + (g >> 1) * 8 + rr) * PKH + kk + (g & 1) * 8) << 1);
                asm volatile("ldmatrix.sync.aligned.m8n8.x4.shared.b16 {%0,%1,%2,%3}, [%4];"
                    : "=r"(b[nj * 2][0]), "=r"(b[nj * 2][1]),
                      "=r"(b[nj * 2 + 1][0]), "=r"(b[nj * 2 + 1][1]) : "r"(bd));
            }
#pragma unroll
            for (int mi = 0; mi < 4; mi++)
#pragma unroll
                for (int ni = 0; ni < 4; ni++)
                    asm volatile(
                        "mma.sync.aligned.m16n8k16.row.col.f32.bf16.bf16.f32 "
                        "{%0,%1,%2,%3}, {%4,%5,%6,%7}, {%8,%9}, {%0,%1,%2,%3};"
                        : "+f"(c[mi][ni][0]), "+f"(c[mi][ni][1]),
                          "+f"(c[mi][ni][2]), "+f"(c[mi][ni][3])
                        : "r"(a[mi][0]), "r"(a[mi][1]), "r"(a[mi][2]), "r"(a[mi][3]),
                          "r"(b[ni][0]), "r"(b[ni][1]));
        }

        if (kt + 1 < nk) {
            const int nxt = cur ^ 1;
            *reinterpret_cast<uint4*>(&As[nxt][lrow * PKH + lcol]) = pa0;
            *reinterpret_cast<uint4*>(&As[nxt][(lrow + 64) * PKH + lcol]) = pa1;
            *reinterpret_cast<uint4*>(&Bs[nxt][lrow * PKH + lcol]) = pb0;
            *reinterpret_cast<uint4*>(&Bs[nxt][(lrow + 64) * PKH + lcol]) = pb1;
            __syncthreads();
        }
    }

#pragma unroll
    for (int mi = 0; mi < 4; mi++) {
        const int row = m0 + wm * 64 + mi * 16 + (lane >> 2);
#pragma unroll
        for (int ni = 0; ni < 4; ni++) {
            const int col = n0 + wn * 32 + ni * 8 + (lane & 3) * 2;
            const float bx = bias[col], by = bias[col + 1];
            float2 v0 = make_float2(c[mi][ni][0] + bx, c[mi][ni][1] + by);
            float2 v1 = make_float2(c[mi][ni][2] + bx, c[mi][ni][3] + by);
            *reinterpret_cast<float2*>(&C[(size_t)row * N + col]) = v0;
            *reinterpret_cast<float2*>(&C[(size_t)(row + 8) * N + col]) = v1;
        }
    }
}

// ---------------- grid barrier (monotonic counter) ----------------
__device__ __forceinline__ void grid_barrier(unsigned& tgt, unsigned nctas) {
    __threadfence();
    __syncthreads();
    if (threadIdx.x == 0) {
        tgt += nctas;
        const unsigned t = tgt;
        const unsigned v = atomicAdd(&g_bar, 1u) + 1u;
        if (v != t) {
            while (*reinterpret_cast<volatile unsigned*>(&g_bar) < t) {}
        }
        __threadfence();
    }
    __syncthreads();
}

// ---------------- tensor-core persistent BiGRU recurrence ----------------
// 128 CTAs: dir = cta>>6, k-slice (8 cols) = cta&63.  256 threads, 8 warps.
// Per step: C[64 b x 24 g] = h3[64 x 1024] x W3slice via 3-term bf16 split.
#define PA 1032   // A smem pitch (halves)
#define PW 520    // W smem pitch (halves)
__global__ void __launch_bounds__(256, 1) recur_tc_kernel(
    const float* __restrict__ xp,    // [dir][B*T, 1536] (includes b_ih)
    const float* __restrict__ w_hh,  // [2][1536][512]
    const float* __restrict__ b_hh,  // [2][1536]
    float* __restrict__ y,           // [B*T, 1024] or nullptr
    int do_pool)
{
    extern __shared__ char smraw[];
    __nv_bfloat16* sWhi = reinterpret_cast<__nv_bfloat16*>(smraw);   // [24][PW]
    __nv_bfloat16* sWlo = sWhi + 24 * PW;                             // [24][PW]
    __nv_bfloat16* sA   = sWlo + 24 * PW;                             // [64][PA]
    float* sgh   = reinterpret_cast<float*>(sA + 64 * PA);            // [64][25]
    float* sred  = sgh + 64 * 25;                                     // [128][12]
    float* shsl  = sred + 128 * 12;                                   // [8][65] fp32 h slice
    float* sbias = shsl + 8 * 65;                                     // [24]

    const int cta = blockIdx.x;
    const int dir = cta >> 6;
    const int k0  = (cta & 63) * 8;
    const int tid = threadIdx.x;
    const int warp = tid >> 5, lane = tid & 31;
    const int wm = warp & 3, kh = warp >> 2;

    // ---- load + split W_hh slice: rows jj = g*8+rc -> global row g*512+k0+rc
    {
        const float* wsrc = w_hh + (size_t)dir * GG * HH;
        for (int idx = tid; idx < 24 * 128; idx += 256) {
            const int jj = idx >> 7;
            const int q  = (idx & 127) * 4;
            const int grow = (jj >> 3) * HH + k0 + (jj & 7);
            const float4 v = *reinterpret_cast<const float4*>(&wsrc[(size_t)grow * HH + q]);
            const __nv_bfloat16 h0 = __float2bfloat16(v.x), h1 = __float2bfloat16(v.y);
            const __nv_bfloat16 h2 = __float2bfloat16(v.z), h3 = __float2bfloat16(v.w);
            const __nv_bfloat16 l0 = __float2bfloat16(v.x - __bfloat162float(h0));
            const __nv_bfloat16 l1 = __float2bfloat16(v.y - __bfloat162float(h1));
            const __nv_bfloat16 l2 = __float2bfloat16(v.z - __bfloat162float(h2));
            const __nv_bfloat16 l3 = __float2bfloat16(v.w - __bfloat162float(h3));
            __nv_bfloat162* dh = reinterpret_cast<__nv_bfloat162*>(sWhi + jj * PW + q);
            __nv_bfloat162* dl = reinterpret_cast<__nv_bfloat162*>(sWlo + jj * PW + q);
            dh[0] = __halves2bfloat162(h0, h1); dh[1] = __halves2bfloat162(h2, h3);
            dl[0] = __halves2bfloat162(l0, l1); dl[1] = __halves2bfloat162(l2, l3);
        }
        if (tid < 24)
            sbias[tid] = b_hh[dir * GG + (tid >> 3) * HH + k0 + (tid & 7)];
        for (int i = tid; i < 8 * 65; i += 256) shsl[i] = 0.f;
    }
    __syncthreads();

    const int b_ep = tid >> 2;               // epilogue batch
    const int kbase = (tid & 3) * 2;         // epilogue k pair base
    float mx[2] = {-1e30f, -1e30f};
    unsigned bar_tgt = 0;

    const unsigned sAb  = (unsigned)__cvta_generic_to_shared(sA);
    const unsigned sWhb = (unsigned)__cvta_generic_to_shared(sWhi);
    const unsigned sWlb = (unsigned)__cvta_generic_to_shared(sWlo);

    for (int s = 0; s < TT; s++) {
        const int t = dir ? (TT - 1 - s) : s;
        const int p = s & 1;

        // ---- broadcast-in: load h3 [64 x 1024 halves] (L2-coherent)
        {
            const uint4* src = reinterpret_cast<const uint4*>(&g_hA[p][dir][0][0]);
#pragma unroll
            for (int i = 0; i < 32; i++) {
                const int idx = tid + i * 256;
                const int row = idx >> 7, col = idx & 127;
                const uint4 v = __ldcg(src + idx);
                *reinterpret_cast<uint4*>(sA + row * PA + col * 8) = v;
            }
        }
        __syncthreads();

        // ---- mma: 3 split passes, k-half per warp
        float cr[4] = {0.f, 0.f, 0.f, 0.f};
        float cz[4] = {0.f, 0.f, 0.f, 0.f};
        float cn[4] = {0.f, 0.f, 0.f, 0.f};

#define MMA_PASS(AOFF, WSB)                                                          \
        for (int kk = kh * 256; kk < kh * 256 + 256; kk += 16) {                     \
            unsigned a0, a1, a2, a3, b00, b01, b10, b11, b20, b21;                   \
            const unsigned ad = sAb +                                                \
                ((((wm * 16 + (lane & 15)) * PA) + (AOFF) + kk + (lane >> 4) * 8) << 1); \
            asm volatile("ldmatrix.sync.aligned.m8n8.x4.shared.b16 {%0,%1,%2,%3}, [%4];" \
                : "=r"(a0), "=r"(a1), "=r"(a2), "=r"(a3) : "r"(ad));                 \
            const int g_ = lane >> 3, rr_ = lane & 7;                                \
            const unsigned bd = (WSB) +                                              \
                ((((g_ >> 1) * 8 + rr_) * PW + kk + (g_ & 1) * 8) << 1);             \
            asm volatile("ldmatrix.sync.aligned.m8n8.x4.shared.b16 {%0,%1,%2,%3}, [%4];" \
                : "=r"(b00), "=r"(b01), "=r"(b10), "=r"(b11) : "r"(bd));             \
            const unsigned bd2 = (WSB) +                                             \
                (((16 + rr_) * PW + kk + ((lane >> 3) & 1) * 8) << 1);               \
            asm volatile("ldmatrix.sync.aligned.m8n8.x2.shared.b16 {%0,%1}, [%2];"   \
                : "=r"(b20), "=r"(b21) : "r"(bd2));                                  \
            asm volatile("mma.sync.aligned.m16n8k16.row.col.f32.bf16.bf16.f32 "      \
                "{%0,%1,%2,%3}, {%4,%5,%6,%7}, {%8,%9}, {%0,%1,%2,%3};"              \
                : "+f"(cr[0]), "+f"(cr[1]), "+f"(cr[2]), "+f"(cr[3])                 \
                : "r"(a0), "r"(a1), "r"(a2), "r"(a3), "r"(b00), "r"(b01));           \
            asm volatile("mma.sync.aligned.m16n8k16.row.col.f32.bf16.bf16.f32 "      \
                "{%0,%1,%2,%3}, {%4,%5,%6,%7}, {%8,%9}, {%0,%1,%2,%3};"              \
                : "+f"(cz[0]), "+f"(cz[1]), "+f"(cz[2]), "+f"(cz[3])                 \
                : "r"(a0), "r"(a1), "r"(a2), "r"(a3), "r"(b10), "r"(b11));           \
            asm volatile("mma.sync.aligned.m16n8k16.row.col.f32.bf16.bf16.f32 "      \
                "{%0,%1,%2,%3}, {%4,%5,%6,%7}, {%8,%9}, {%0,%1,%2,%3};"              \
                : "+f"(cn[0]), "+f"(cn[1]), "+f"(cn[2]), "+f"(cn[3])                 \
                : "r"(a0), "r"(a1), "r"(a2), "r"(a3), "r"(b20), "r"(b21));           \
        }

        MMA_PASS(0,   sWhb)   // hi * Whi
        MMA_PASS(0,   sWlb)   // hi * Wlo
        MMA_PASS(512, sWhb)   // lo * Whi

        // ---- reduce k-halves
        if (kh == 1) {
            float* rp = sred + (size_t)((warp - 4) * 32 + lane) * 12;
#pragma unroll
            for (int q = 0; q < 4; q++) {
                rp[q] = cr[q]; rp[4 + q] = cz[q]; rp[8 + q] = cn[q];
            }
        }
        __syncthreads();
        if (kh == 0) {
            const float* rp = sred + (size_t)(warp * 32 + lane) * 12;
#pragma unroll
            for (int q = 0; q < 4; q++) {
                cr[q] += rp[q]; cz[q] += rp[4 + q]; cn[q] += rp[8 + q];
            }
            // scatter gh to smem [64][25]: row=batch, col = gate*8 + kc
#pragma unroll
            for (int q = 0; q < 4; q++) {
                const int row = wm * 16 + (lane >> 2) + (q >> 1) * 8;
                const int col = (lane & 3) * 2 + (q & 1);
                sgh[row * 25 + col]      = cr[q];
                sgh[row * 25 + 8 + col]  = cz[q];
                sgh[row * 25 + 16 + col] = cn[q];
            }
        }
        __syncthreads();

        // ---- epilogue: 2 cells per thread (b_ep, kbase..kbase+1)
        {
            const size_t base = ((size_t)(dir * BB + b_ep) * TT + t) * GG + k0 + kbase;
            const float2 xr = *reinterpret_cast<const float2*>(xp + base);
            const float2 xz = *reinterpret_cast<const float2*>(xp + base + HH);
            const float2 xn = *reinterpret_cast<const float2*>(xp + base + 2 * HH);
            float hv[2];
#pragma unroll
            for (int j = 0; j < 2; j++) {
                const int kc = kbase + j;
                const float gr = sgh[b_ep * 25 + kc]      + sbias[kc];
                const float gz = sgh[b_ep * 25 + 8 + kc]  + sbias[8 + kc];
                const float gn = sgh[b_ep * 25 + 16 + kc] + sbias[16 + kc];
                const float xrv = j ? xr.y : xr.x;
                const float xzv = j ? xz.y : xz.x;
                const float xnv = j ? xn.y : xn.x;
                const float rg = 1.f / (1.f + expf(-(xrv + gr)));
                const float zg = 1.f / (1.f + expf(-(xzv + gz)));
                const float ng = tanhf(xnv + rg * gn);
                const float hp = shsl[kc * 65 + b_ep];
                hv[j] = (1.f - zg) * ng + zg * hp;
                shsl[kc * 65 + b_ep] = hv[j];
                if (do_pool) mx[j] = fmaxf(mx[j], hv[j]);
            }
            // write bf16 split to next buffer (hi pair + lo pair)
            const __nv_bfloat16 h0 = __float2bfloat16(hv[0]);
            const __nv_bfloat16 h1 = __float2bfloat16(hv[1]);
            const __nv_bfloat16 l0 = __float2bfloat16(hv[0] - __bfloat162float(h0));
            const __nv_bfloat16 l1 = __float2bfloat16(hv[1] - __bfloat162float(h1));
            const __nv_bfloat162 hp2 = __halves2bfloat162(h0, h1);
            const __nv_bfloat162 lp2 = __halves2bfloat162(l0, l1);
            __nv_bfloat16* dst = &g_hA[1 - p][dir][b_ep][k0 + kbase];
            __stcg(reinterpret_cast<unsigned*>(dst),
                   *reinterpret_cast<const unsigned*>(&hp2));
            __stcg(reinterpret_cast<unsigned*>(dst + 512),
                   *reinterpret_cast<const unsigned*>(&lp2));
            if (y) {
                float2 yv = make_float2(hv[0], hv[1]);
                *reinterpret_cast<float2*>(
                    &y[((size_t)b_ep * TT + t) * (2 * HH) + dir * HH + k0 + kbase]) = yv;
            }
        }
        grid_barrier(bar_tgt, gridDim.x);
    }

    if (do_pool) {
        g_pooled[(size_t)b_ep * (2 * HH) + dir * HH + k0 + kbase]     = mx[0];
        g_pooled[(size_t)b_ep * (2 * HH) + dir * HH + k0 + kbase + 1] = mx[1];
    }
}

// ---------------- classifier head ----------------
__global__ void mlp1_kernel(const float* __restrict__ w1, const float* __restrict__ b1) {
    const int warp = (blockIdx.x * blockDim.x + threadIdx.x) >> 5;
    const int lane = threadIdx.x & 31;
    if (warp >= BB * 128) return;
    const int b = warp >> 7, j = warp & 127;
    const float* p = g_pooled + (size_t)b * 2 * HH;
    const float* w = w1 + (size_t)j * 2 * HH;
    float s = 0.f;
    for (int k = lane; k < 2 * HH; k += 32) s = fmaf(p[k], w[k], s);
#pragma unroll
    for (int o = 16; o; o >>= 1) s += __shfl_xor_sync(0xffffffffu, s, o);
    if (lane == 0) g_hid[b * 128 + j] = fmaxf(s + b1[j], 0.f);
}

__global__ void mlp2_kernel(const float* __restrict__ w2, const float* __restrict__ b2,
                            float* __restrict__ out) {
    const int t = threadIdx.x;
    if (t < BB * 2) {
        const int b = t >> 1, c = t & 1;
        float s = b2[c];
        const float* h = g_hid + b * 128;
        const float* w = w2 + c * 128;
        for (int k = 0; k < 128; k++) s = fmaf(h[k], w[k], s);
        out[t] = s;
    }
}

// ---------------- launch ----------------
extern "C" void kernel_launch(void* const* d_in, const int* in_sizes, int n_in,
                              void* d_out, int out_size) {
    const int*   x    = (const int*)d_in[0];
    const float* emb  = (const float*)d_in[1];
    const float* wih0 = (const float*)d_in[2];
    const float* whh0 = (const float*)d_in[3];
    const float* bih0 = (const float*)d_in[4];
    const float* bhh0 = (const float*)d_in[5];
    const float* wih1 = (const float*)d_in[6];
    const float* whh1 = (const float*)d_in[7];
    const float* bih1 = (const float*)d_in[8];
    const float* bhh1 = (const float*)d_in[9];
    const float* w1   = (const float*)d_in[10];
    const float* b1   = (const float*)d_in[11];
    const float* w2   = (const float*)d_in[12];
    const float* b2   = (const float*)d_in[13];

    float *e_p = nullptr, *xp_p = nullptr, *y0_p = nullptr;
    __nv_bfloat16 *a3_p = nullptr, *w3_p = nullptr;
    cudaGetSymbolAddress((void**)&e_p,  g_e);
    cudaGetSymbolAddress((void**)&xp_p, g_xp);
    cudaGetSymbolAddress((void**)&y0_p, g_y0);
    cudaGetSymbolAddress((void**)&a3_p, g_a3);
    cudaGetSymbolAddress((void**)&w3_p, g_w3);

    const size_t sm_tc = (size_t)(2 * 24 * PW + 64 * PA) * sizeof(__nv_bfloat16)
                       + (size_t)(64 * 25 + 128 * 12 + 8 * 65 + 24) * sizeof(float);
    cudaFuncSetAttribute(recur_tc_kernel, cudaFuncAttributeMaxDynamicSharedMemorySize, (int)sm_tc);

    // ---- layer 0 ----
    init_kernel<<<64, 256>>>();
    embed_kernel<<<MM, 128>>>(x, emb);
    {
        const long pa = (long)MM * (320 / 2);
        conv_split_kernel<<<(unsigned)((pa + 255) / 256), 256>>>(e_p, a3_p, MM, EE, 320, 0);
        const long pw = (long)(2 * GG) * (320 / 2);
        conv_split_kernel<<<(unsigned)((pw + 255) / 256), 256>>>(wih0, w3_p, 2 * GG, EE, 320, 1);
    }
    bgemm_kernel<<<dim3(GG / 128, MM / 128, 2), 256>>>(a3_p, w3_p, bih0, xp_p, MM, GG, 960);
    recur_tc_kernel<<<128, 256, sm_tc>>>(xp_p, whh0, bhh0, y0_p, 0);

    // ---- layer 1 ----
    {
        const long pa = (long)MM * (1024 / 2);
        conv_split_kernel<<<(unsigned)((pa + 255) / 256), 256>>>(y0_p, a3_p, MM, 2 * HH, 1024, 0);
        const long pw = (long)(2 * GG) * (1024 / 2);
        conv_split_kernel<<<(unsigned)((pw + 255) / 256), 256>>>(wih1, w3_p, 2 * GG, 2 * HH, 1024, 1);
    }
    bgemm_kernel<<<dim3(GG / 128, MM / 128, 2), 256>>>(a3_p, w3_p, bih1, xp_p, MM, GG, 3072);
    init_kernel<<<64, 256>>>();
    recur_tc_kernel<<<128, 256, sm_tc>>>(xp_p, whh1, bhh1, nullptr, 1);

    // ---- head ----
    mlp1_kernel<<<(BB * 128 * 32) / 256, 256>>>(w1, b1);
    mlp2_kernel<<<1, 128>>>(w2, b2, (float*)d_out);
}

// round 4
// speedup vs baseline: 2.4406x; 1.1001x over previous
#include <cuda_runtime.h>
#include <cuda_bf16.h>
#include <math.h>

#define BB 64
#define TT 256
#define EE 300
#define HH 512
#define GG 1536               // 3*H
#define MM (BB*TT)            // 16384

// ---------------- scratch (static device allocations only) ----------------
__device__ __align__(256) float g_e[MM * EE];            // embedded input  [B*T, 300]
__device__ __align__(256) float g_xp[2 * MM * GG];       // input projections [dir][B*T, 1536]
__device__ __align__(256) float g_y0[MM * 2 * HH];       // layer0 output [B*T, 1024]
__device__ __align__(256) __nv_bfloat16 g_hA[2][2][BB][1024]; // h split [buf][dir][b][hi|lo]
__device__ __align__(256) float g_pooled[BB * 2 * HH];   // maxpool [B, 1024]
__device__ __align__(256) float g_hid[BB * 128];         // mlp hidden
__device__ __align__(256) __nv_bfloat16 g_a3[MM * 3 * 1024];        // split A [M, 3*Kp]
__device__ __align__(256) __nv_bfloat16 g_w3[2 * GG * 3 * 1024];    // split W [2N, 3*Kp]
__device__ unsigned g_bar;

// ---------------- init: zero hidden split buffers + barrier ----------------
__global__ void init_kernel() {
    const int n = 2 * 2 * BB * 1024 / 2;   // as uint count
    unsigned* p = reinterpret_cast<unsigned*>(&g_hA[0][0][0][0]);
    for (int i = blockIdx.x * blockDim.x + threadIdx.x; i < n; i += gridDim.x * blockDim.x)
        p[i] = 0u;
    if (blockIdx.x == 0 && threadIdx.x == 0) g_bar = 0u;
}

// ---------------- embedding gather ----------------
__global__ void embed_kernel(const int* __restrict__ x, const float* __restrict__ emb) {
    const int tok = blockIdx.x;
    const int row = x[tok];
    const float4* src = reinterpret_cast<const float4*>(emb + (size_t)row * EE);
    float4* dst = reinterpret_cast<float4*>(g_e + (size_t)tok * EE);
    for (int i = threadIdx.x; i < EE / 4; i += blockDim.x) dst[i] = src[i];
}

// ---------------- bf16 split conversion ----------------
// mode 0 (A): slabs = [hi | hi | lo];  mode 1 (W): slabs = [hi | lo | hi]
__global__ void conv_split_kernel(const float* __restrict__ src, __nv_bfloat16* __restrict__ dst,
                                  int rows, int Ksrc, int Kp, int mode) {
    const long i = (long)blockIdx.x * blockDim.x + threadIdx.x;   // pair index
    const long total = (long)rows * (Kp / 2);
    if (i >= total) return;
    const int m  = (int)(i / (Kp / 2));
    const int k0 = (int)(i % (Kp / 2)) * 2;
    const float v0 = (k0     < Ksrc) ? src[(size_t)m * Ksrc + k0]     : 0.f;
    const float v1 = (k0 + 1 < Ksrc) ? src[(size_t)m * Ksrc + k0 + 1] : 0.f;
    const __nv_bfloat16 h0 = __float2bfloat16(v0), h1 = __float2bfloat16(v1);
    const __nv_bfloat16 l0 = __float2bfloat16(v0 - __bfloat162float(h0));
    const __nv_bfloat16 l1 = __float2bfloat16(v1 - __bfloat162float(h1));
    const __nv_bfloat162 hh = __halves2bfloat162(h0, h1);
    const __nv_bfloat162 ll = __halves2bfloat162(l0, l1);
    __nv_bfloat162* d = reinterpret_cast<__nv_bfloat162*>(dst + (size_t)m * 3 * Kp);
    const int p = k0 >> 1, s = Kp >> 1;
    if (mode == 0) { d[p] = hh; d[p + s] = hh; d[p + 2 * s] = ll; }
    else           { d[p] = hh; d[p + s] = ll; d[p + 2 * s] = hh; }
}

// ---------------- bf16 tensor-core GEMM with fused bias ----------------
#define PKH 40
__global__ void __launch_bounds__(256, 2) bgemm_kernel(
    const __nv_bfloat16* __restrict__ A,   // [M, K3]
    const __nv_bfloat16* __restrict__ W,   // [2][N, K3]
    const float* __restrict__ bias,        // [2][N]
    float* __restrict__ C,                 // [2][M, N]
    int M, int N, int K3)
{
    __shared__ __align__(16) __nv_bfloat16 As[2][128 * PKH];
    __shared__ __align__(16) __nv_bfloat16 Bs[2][128 * PKH];

    const int z = blockIdx.z;
    W    += (size_t)z * N * K3;
    bias += (size_t)z * N;
    C    += (size_t)z * M * N;

    const int m0 = blockIdx.y * 128, n0 = blockIdx.x * 128;
    const int tid = threadIdx.x;
    const int warp = tid >> 5, lane = tid & 31;
    const int wm = warp >> 2, wn = warp & 3;

    float c[4][4][4];
#pragma unroll
    for (int mi = 0; mi < 4; mi++)
#pragma unroll
        for (int ni = 0; ni < 4; ni++)
#pragma unroll
            for (int q = 0; q < 4; q++) c[mi][ni][q] = 0.f;

    const int lrow = tid >> 2;
    const int lcol = (tid & 3) * 8;

    {
        const uint4 a0 = *reinterpret_cast<const uint4*>(A + (size_t)(m0 + lrow) * K3 + lcol);
        const uint4 a1 = *reinterpret_cast<const uint4*>(A + (size_t)(m0 + lrow + 64) * K3 + lcol);
        const uint4 b0 = *reinterpret_cast<const uint4*>(W + (size_t)(n0 + lrow) * K3 + lcol);
        const uint4 b1 = *reinterpret_cast<const uint4*>(W + (size_t)(n0 + lrow + 64) * K3 + lcol);
        *reinterpret_cast<uint4*>(&As[0][lrow * PKH + lcol]) = a0;
        *reinterpret_cast<uint4*>(&As[0][(lrow + 64) * PKH + lcol]) = a1;
        *reinterpret_cast<uint4*>(&Bs[0][lrow * PKH + lcol]) = b0;
        *reinterpret_cast<uint4*>(&Bs[0][(lrow + 64) * PKH + lcol]) = b1;
    }
    __syncthreads();

    const int nk = K3 / 32;
    uint4 pa0, pa1, pb0, pb1;

    for (int kt = 0; kt < nk; kt++) {
        const int cur = kt & 1;
        if (kt + 1 < nk) {
            const int kg = (kt + 1) * 32 + lcol;
            pa0 = *reinterpret_cast<const uint4*>(A + (size_t)(m0 + lrow) * K3 + kg);
            pa1 = *reinterpret_cast<const uint4*>(A + (size_t)(m0 + lrow + 64) * K3 + kg);
            pb0 = *reinterpret_cast<const uint4*>(W + (size_t)(n0 + lrow) * K3 + kg);
            pb1 = *reinterpret_cast<const uint4*>(W + (size_t)(n0 + lrow + 64) * K3 + kg);
        }

        const unsigned abase = (unsigned)__cvta_generic_to_shared(&As[cur][0]);
        const unsigned bbase = (unsigned)__cvta_generic_to_shared(&Bs[cur][0]);

#pragma unroll
        for (int kk = 0; kk < 32; kk += 16) {
            unsigned a[4][4], b[4][2];
#pragma unroll
            for (int mi = 0; mi < 4; mi++) {
                const unsigned ad = abase +
                    (((wm * 64 + mi * 16 + (lane & 15)) * PKH + kk + (lane >> 4) * 8) << 1);
                asm volatile("ldmatrix.sync.aligned.m8n8.x4.shared.b16 {%0,%1,%2,%3}, [%4];"
                    : "=r"(a[mi][0]), "=r"(a[mi][1]), "=r"(a[mi][2]), "=r"(a[mi][3]) : "r"(ad));
            }
#pragma unroll
            for (int nj = 0; nj < 2; nj++) {
                const int g = lane >> 3, rr = lane & 7;
                const unsigned bd = bbase +
                    (((wn * 32 + nj * 16 + (g >> 1) * 8 + rr) * PKH + kk + (g & 1) * 8) << 1);
                asm volatile("ldmatrix.sync.aligned.m8n8.x4.shared.b16 {%0,%1,%2,%3}, [%4];"
                    : "=r"(b[nj * 2][0]), "=r"(b[nj * 2][1]),
                      "=r"(b[nj * 2 + 1][0]), "=r"(b[nj * 2 + 1][1]) : "r"(bd));
            }
#pragma unroll
            for (int mi = 0; mi < 4; mi++)
#pragma unroll
                for (int ni = 0; ni < 4; ni++)
                    asm volatile(
                        "mma.sync.aligned.m16n8k16.row.col.f32.bf16.bf16.f32 "
                        "{%0,%1,%2,%3}, {%4,%5,%6,%7}, {%8,%9}, {%0,%1,%2,%3};"
                        : "+f"(c[mi][ni][0]), "+f"(c[mi][ni][1]),
                          "+f"(c[mi][ni][2]), "+f"(c[mi][ni][3])
                        : "r"(a[mi][0]), "r"(a[mi][1]), "r"(a[mi][2]), "r"(a[mi][3]),
                          "r"(b[ni][0]), "r"(b[ni][1]));
        }

        if (kt + 1 < nk) {
            const int nxt = cur ^ 1;
            *reinterpret_cast<uint4*>(&As[nxt][lrow * PKH + lcol]) = pa0;
            *reinterpret_cast<uint4*>(&As[nxt][(lrow + 64) * PKH + lcol]) = pa1;
            *reinterpret_cast<uint4*>(&Bs[nxt][lrow * PKH + lcol]) = pb0;
            *reinterpret_cast<uint4*>(&Bs[nxt][(lrow + 64) * PKH + lcol]) = pb1;
            __syncthreads();
        }
    }

#pragma unroll
    for (int mi = 0; mi < 4; mi++) {
        const int row = m0 + wm * 64 + mi * 16 + (lane >> 2);
#pragma unroll
        for (int ni = 0; ni < 4; ni++) {
            const int col = n0 + wn * 32 + ni * 8 + (lane & 3) * 2;
            const float bx = bias[col], by = bias[col + 1];
            float2 v0 = make_float2(c[mi][ni][0] + bx, c[mi][ni][1] + by);
            float2 v1 = make_float2(c[mi][ni][2] + bx, c[mi][ni][3] + by);
            *reinterpret_cast<float2*>(&C[(size_t)row * N + col]) = v0;
            *reinterpret_cast<float2*>(&C[(size_t)(row + 8) * N + col]) = v1;
        }
    }
}

// ---------------- grid barrier (release/acquire, monotonic counter) ----------------
__device__ __forceinline__ void grid_barrier(unsigned& tgt, unsigned nctas) {
    __syncthreads();
    if (threadIdx.x == 0) {
        tgt += nctas;
        const unsigned t = tgt;
        unsigned prev;
        asm volatile("atom.acq_rel.gpu.global.add.u32 %0, [%1], 1;"
                     : "=r"(prev) : "l"(&g_bar) : "memory");
        if (prev + 1u != t) {
            unsigned v;
            do {
                asm volatile("ld.acquire.gpu.global.u32 %0, [%1];"
                             : "=r"(v) : "l"(&g_bar) : "memory");
            } while (v < t);
        }
    }
    __syncthreads();
}

// ---------------- tensor-core persistent BiGRU recurrence ----------------
// 128 CTAs: dir = cta>>6, k-slice (8 cols) = cta&63.  256 threads, 8 warps.
// Per step: C[64 b x 24 g] = h3[64 x 1024] x W3slice via 3-term bf16 split.
// h broadcast pipelined with cp.async (4 x 32KB chunks, hi chunks first).
#define PA 1032   // A smem pitch (halves)
#define PW 520    // W smem pitch (halves)
__global__ void __launch_bounds__(256, 1) recur_tc_kernel(
    const float* __restrict__ xp,    // [dir][B*T, 1536] (includes b_ih)
    const float* __restrict__ w_hh,  // [2][1536][512]
    const float* __restrict__ b_hh,  // [2][1536]
    float* __restrict__ y,           // [B*T, 1024] or nullptr
    int do_pool)
{
    extern __shared__ char smraw[];
    __nv_bfloat16* sWhi = reinterpret_cast<__nv_bfloat16*>(smraw);   // [24][PW]
    __nv_bfloat16* sWlo = sWhi + 24 * PW;                             // [24][PW]
    __nv_bfloat16* sA   = sWlo + 24 * PW;                             // [64][PA]
    float* sgh   = reinterpret_cast<float*>(sA + 64 * PA);            // [64][25]
    float* sred  = sgh + 64 * 25;                                     // [128][12]
    float* shsl  = sred + 128 * 12;                                   // [8][65] fp32 h slice
    float* sbias = shsl + 8 * 65;                                     // [24]

    const int cta = blockIdx.x;
    const int dir = cta >> 6;
    const int k0  = (cta & 63) * 8;
    const int tid = threadIdx.x;
    const int warp = tid >> 5, lane = tid & 31;
    const int wm = warp & 3, kh = warp >> 2;

    // ---- load + split W_hh slice
    {
        const float* wsrc = w_hh + (size_t)dir * GG * HH;
        for (int idx = tid; idx < 24 * 128; idx += 256) {
            const int jj = idx >> 7;
            const int q  = (idx & 127) * 4;
            const int grow = (jj >> 3) * HH + k0 + (jj & 7);
            const float4 v = *reinterpret_cast<const float4*>(&wsrc[(size_t)grow * HH + q]);
            const __nv_bfloat16 h0 = __float2bfloat16(v.x), h1 = __float2bfloat16(v.y);
            const __nv_bfloat16 h2 = __float2bfloat16(v.z), h3 = __float2bfloat16(v.w);
            const __nv_bfloat16 l0 = __float2bfloat16(v.x - __bfloat162float(h0));
            const __nv_bfloat16 l1 = __float2bfloat16(v.y - __bfloat162float(h1));
            const __nv_bfloat16 l2 = __float2bfloat16(v.z - __bfloat162float(h2));
            const __nv_bfloat16 l3 = __float2bfloat16(v.w - __bfloat162float(h3));
            __nv_bfloat162* dh = reinterpret_cast<__nv_bfloat162*>(sWhi + jj * PW + q);
            __nv_bfloat162* dl = reinterpret_cast<__nv_bfloat162*>(sWlo + jj * PW + q);
            dh[0] = __halves2bfloat162(h0, h1); dh[1] = __halves2bfloat162(h2, h3);
            dl[0] = __halves2bfloat162(l0, l1); dl[1] = __halves2bfloat162(l2, l3);
        }
        if (tid < 24)
            sbias[tid] = b_hh[dir * GG + (tid >> 3) * HH + k0 + (tid & 7)];
        for (int i = tid; i < 8 * 65; i += 256) shsl[i] = 0.f;
    }
    __syncthreads();

    const int b_ep = tid >> 2;               // epilogue batch
    const int kbase = (tid & 3) * 2;         // epilogue k pair base
    float mx[2] = {-1e30f, -1e30f};
    unsigned bar_tgt = 0;

    const unsigned sAb  = (unsigned)__cvta_generic_to_shared(sA);
    const unsigned sWhb = (unsigned)__cvta_generic_to_shared(sWhi);
    const unsigned sWlb = (unsigned)__cvta_generic_to_shared(sWlo);

    // cp.async addressing: per chunk 8 iters, row = idx>>5, seg = idx&31
    const int cp_row = 0;  (void)cp_row;

    for (int s = 0; s < TT; s++) {
        const int t = dir ? (TT - 1 - s) : s;
        const int p = s & 1;

        // ---- prefetch xp epilogue operands (independent of h)
        const size_t xbase = ((size_t)(dir * BB + b_ep) * TT + t) * GG + k0 + kbase;
        const float2 xr = __ldg(reinterpret_cast<const float2*>(xp + xbase));
        const float2 xz = __ldg(reinterpret_cast<const float2*>(xp + xbase + HH));
        const float2 xn = __ldg(reinterpret_cast<const float2*>(xp + xbase + 2 * HH));

        // ---- issue h3 broadcast: 4 x 32KB cp.async chunks (cols 0..255, 256.., 512.., 768..)
        {
            const __nv_bfloat16* hsrc = &g_hA[p][dir][0][0];
#pragma unroll
            for (int c = 0; c < 4; c++) {
#pragma unroll
                for (int it = 0; it < 8; it++) {
                    const int idx = it * 256 + tid;
                    const int row = idx >> 5, seg = idx & 31;
                    const int col = c * 256 + seg * 8;
                    const unsigned d = sAb + (unsigned)((row * PA + col) << 1);
                    const __nv_bfloat16* gp = hsrc + row * 1024 + col;
                    asm volatile("cp.async.cg.shared.global [%0], [%1], 16;"
                                 :: "r"(d), "l"(gp) : "memory");
                }
                asm volatile("cp.async.commit_group;" ::: "memory");
            }
        }

        float cr[4] = {0.f, 0.f, 0.f, 0.f};
        float cz[4] = {0.f, 0.f, 0.f, 0.f};
        float cn[4] = {0.f, 0.f, 0.f, 0.f};

#define MMA_PASS(AOFF, WSB)                                                          \
        for (int kk = kh * 256; kk < kh * 256 + 256; kk += 16) {                     \
            unsigned a0, a1, a2, a3, b00, b01, b10, b11, b20, b21;                   \
            const unsigned ad = sAb +                                                \
                ((((wm * 16 + (lane & 15)) * PA) + (AOFF) + kk + (lane >> 4) * 8) << 1); \
            asm volatile("ldmatrix.sync.aligned.m8n8.x4.shared.b16 {%0,%1,%2,%3}, [%4];" \
                : "=r"(a0), "=r"(a1), "=r"(a2), "=r"(a3) : "r"(ad));                 \
            const int g_ = lane >> 3, rr_ = lane & 7;                                \
            const unsigned bd = (WSB) +                                              \
                ((((g_ >> 1) * 8 + rr_) * PW + kk + (g_ & 1) * 8) << 1);             \
            asm volatile("ldmatrix.sync.aligned.m8n8.x4.shared.b16 {%0,%1,%2,%3}, [%4];" \
                : "=r"(b00), "=r"(b01), "=r"(b10), "=r"(b11) : "r"(bd));             \
            const unsigned bd2 = (WSB) +                                             \
                (((16 + rr_) * PW + kk + ((lane >> 3) & 1) * 8) << 1);               \
            asm volatile("ldmatrix.sync.aligned.m8n8.x2.shared.b16 {%0,%1}, [%2];"   \
                : "=r"(b20), "=r"(b21) : "r"(bd2));                                  \
            asm volatile("mma.sync.aligned.m16n8k16.row.col.f32.bf16.bf16.f32 "      \
                "{%0,%1,%2,%3}, {%4,%5,%6,%7}, {%8,%9}, {%0,%1,%2,%3};"              \
                : "+f"(cr[0]), "+f"(cr[1]), "+f"(cr[2]), "+f"(cr[3])                 \
                : "r"(a0), "r"(a1), "r"(a2), "r"(a3), "r"(b00), "r"(b01));           \
            asm volatile("mma.sync.aligned.m16n8k16.row.col.f32.bf16.bf16.f32 "      \
                "{%0,%1,%2,%3}, {%4,%5,%6,%7}, {%8,%9}, {%0,%1,%2,%3};"              \
                : "+f"(cz[0]), "+f"(cz[1]), "+f"(cz[2]), "+f"(cz[3])                 \
                : "r"(a0), "r"(a1), "r"(a2), "r"(a3), "r"(b10), "r"(b11));           \
            asm volatile("mma.sync.aligned.m16n8k16.row.col.f32.bf16.bf16.f32 "      \
                "{%0,%1,%2,%3}, {%4,%5,%6,%7}, {%8,%9}, {%0,%1,%2,%3};"              \
                : "+f"(cn[0]), "+f"(cn[1]), "+f"(cn[2]), "+f"(cn[3])                 \
                : "r"(a0), "r"(a1), "r"(a2), "r"(a3), "r"(b20), "r"(b21));           \
        }

        // ---- hi chunks ready (2 groups still pending = chunks 2,3)
        asm volatile("cp.async.wait_group 2;" ::: "memory");
        __syncthreads();
        MMA_PASS(0,   sWhb)   // hi * Whi
        MMA_PASS(0,   sWlb)   // hi * Wlo
        // ---- lo chunks ready
        asm volatile("cp.async.wait_group 0;" ::: "memory");
        __syncthreads();
        MMA_PASS(512, sWhb)   // lo * Whi

        // ---- reduce k-halves
        if (kh == 1) {
            float* rp = sred + (size_t)((warp - 4) * 32 + lane) * 12;
#pragma unroll
            for (int q = 0; q < 4; q++) {
                rp[q] = cr[q]; rp[4 + q] = cz[q]; rp[8 + q] = cn[q];
            }
        }
        __syncthreads();
        if (kh == 0) {
            const float* rp = sred + (size_t)(warp * 32 + lane) * 12;
#pragma unroll
            for (int q = 0; q < 4; q++) {
                cr[q] += rp[q]; cz[q] += rp[4 + q]; cn[q] += rp[8 + q];
            }
#pragma unroll
            for (int q = 0; q < 4; q++) {
                const int row = wm * 16 + (lane >> 2) + (q >> 1) * 8;
                const int col = (lane & 3) * 2 + (q & 1);
                sgh[row * 25 + col]      = cr[q];
                sgh[row * 25 + 8 + col]  = cz[q];
                sgh[row * 25 + 16 + col] = cn[q];
            }
        }
        __syncthreads();

        // ---- epilogue: 2 cells per thread
        {
            float hv[2];
#pragma unroll
            for (int j = 0; j < 2; j++) {
                const int kc = kbase + j;
                const float gr = sgh[b_ep * 25 + kc]      + sbias[kc];
                const float gz = sgh[b_ep * 25 + 8 + kc]  + sbias[8 + kc];
                const float gn = sgh[b_ep * 25 + 16 + kc] + sbias[16 + kc];
                const float xrv = j ? xr.y : xr.x;
                const float xzv = j ? xz.y : xz.x;
                const float xnv = j ? xn.y : xn.x;
                const float rg = 1.f / (1.f + expf(-(xrv + gr)));
                const float zg = 1.f / (1.f + expf(-(xzv + gz)));
                const float ng = tanhf(xnv + rg * gn);
                const float hp = shsl[kc * 65 + b_ep];
                hv[j] = (1.f - zg) * ng + zg * hp;
                shsl[kc * 65 + b_ep] = hv[j];
                if (do_pool) mx[j] = fmaxf(mx[j], hv[j]);
            }
            const __nv_bfloat16 h0 = __float2bfloat16(hv[0]);
            const __nv_bfloat16 h1 = __float2bfloat16(hv[1]);
            const __nv_bfloat16 l0 = __float2bfloat16(hv[0] - __bfloat162float(h0));
            const __nv_bfloat16 l1 = __float2bfloat16(hv[1] - __bfloat162float(h1));
            const __nv_bfloat162 hp2 = __halves2bfloat162(h0, h1);
            const __nv_bfloat162 lp2 = __halves2bfloat162(l0, l1);
            __nv_bfloat16* dst = &g_hA[1 - p][dir][b_ep][k0 + kbase];
            __stcg(reinterpret_cast<unsigned*>(dst),
                   *reinterpret_cast<const unsigned*>(&hp2));
            __stcg(reinterpret_cast<unsigned*>(dst + 512),
                   *reinterpret_cast<const unsigned*>(&lp2));
            if (y) {
                float2 yv = make_float2(hv[0], hv[1]);
                *reinterpret_cast<float2*>(
                    &y[((size_t)b_ep * TT + t) * (2 * HH) + dir * HH + k0 + kbase]) = yv;
            }
        }
        grid_barrier(bar_tgt, gridDim.x);
    }

    if (do_pool) {
        g_pooled[(size_t)b_ep * (2 * HH) + dir * HH + k0 + kbase]     = mx[0];
        g_pooled[(size_t)b_ep * (2 * HH) + dir * HH + k0 + kbase + 1] = mx[1];
    }
}

// ---------------- classifier head ----------------
__global__ void mlp1_kernel(const float* __restrict__ w1, const float* __restrict__ b1) {
    const int warp = (blockIdx.x * blockDim.x + threadIdx.x) >> 5;
    const int lane = threadIdx.x & 31;
    if (warp >= BB * 128) return;
    const int b = warp >> 7, j = warp & 127;
    const float* p = g_pooled + (size_t)b * 2 * HH;
    const float* w = w1 + (size_t)j * 2 * HH;
    float s = 0.f;
    for (int k = lane; k < 2 * HH; k += 32) s = fmaf(p[k], w[k], s);
#pragma unroll
    for (int o = 16; o; o >>= 1) s += __shfl_xor_sync(0xffffffffu, s, o);
    if (lane == 0) g_hid[b * 128 + j] = fmaxf(s + b1[j], 0.f);
}

__global__ void mlp2_kernel(const float* __restrict__ w2, const float* __restrict__ b2,
                            float* __restrict__ out) {
    const int t = threadIdx.x;
    if (t < BB * 2) {
        const int b = t >> 1, c = t & 1;
        float s = b2[c];
        const float* h = g_hid + b * 128;
        const float* w = w2 + c * 128;
        for (int k = 0; k < 128; k++) s = fmaf(h[k], w[k], s);
        out[t] = s;
    }
}

// ---------------- launch ----------------
extern "C" void kernel_launch(void* const* d_in, const int* in_sizes, int n_in,
                              void* d_out, int out_size) {
    const int*   x    = (const int*)d_in[0];
    const float* emb  = (const float*)d_in[1];
    const float* wih0 = (const float*)d_in[2];
    const float* whh0 = (const float*)d_in[3];
    const float* bih0 = (const float*)d_in[4];
    const float* bhh0 = (const float*)d_in[5];
    const float* wih1 = (const float*)d_in[6];
    const float* whh1 = (const float*)d_in[7];
    const float* bih1 = (const float*)d_in[8];
    const float* bhh1 = (const float*)d_in[9];
    const float* w1   = (const float*)d_in[10];
    const float* b1   = (const float*)d_in[11];
    const float* w2   = (const float*)d_in[12];
    const float* b2   = (const float*)d_in[13];

    float *e_p = nullptr, *xp_p = nullptr, *y0_p = nullptr;
    __nv_bfloat16 *a3_p = nullptr, *w3_p = nullptr;
    cudaGetSymbolAddress((void**)&e_p,  g_e);
    cudaGetSymbolAddress((void**)&xp_p, g_xp);
    cudaGetSymbolAddress((void**)&y0_p, g_y0);
    cudaGetSymbolAddress((void**)&a3_p, g_a3);
    cudaGetSymbolAddress((void**)&w3_p, g_w3);

    const size_t sm_tc = (size_t)(2 * 24 * PW + 64 * PA) * sizeof(__nv_bfloat16)
                       + (size_t)(64 * 25 + 128 * 12 + 8 * 65 + 24) * sizeof(float);
    cudaFuncSetAttribute(recur_tc_kernel, cudaFuncAttributeMaxDynamicSharedMemorySize, (int)sm_tc);

    // ---- layer 0 ----
    init_kernel<<<64, 256>>>();
    embed_kernel<<<MM, 128>>>(x, emb);
    {
        const long pa = (long)MM * (320 / 2);
        conv_split_kernel<<<(unsigned)((pa + 255) / 256), 256>>>(e_p, a3_p, MM, EE, 320, 0);
        const long pw = (long)(2 * GG) * (320 / 2);
        conv_split_kernel<<<(unsigned)((pw + 255) / 256), 256>>>(wih0, w3_p, 2 * GG, EE, 320, 1);
    }
    bgemm_kernel<<<dim3(GG / 128, MM / 128, 2), 256>>>(a3_p, w3_p, bih0, xp_p, MM, GG, 960);
    recur_tc_kernel<<<128, 256, sm_tc>>>(xp_p, whh0, bhh0, y0_p, 0);

    // ---- layer 1 ----
    {
        const long pa = (long)MM * (1024 / 2);
        conv_split_kernel<<<(unsigned)((pa + 255) / 256), 256>>>(y0_p, a3_p, MM, 2 * HH, 1024, 0);
        const long pw = (long)(2 * GG) * (1024 / 2);
        conv_split_kernel<<<(unsigned)((pw + 255) / 256), 256>>>(wih1, w3_p, 2 * GG, 2 * HH, 1024, 1);
    }
    bgemm_kernel<<<dim3(GG / 128, MM / 128, 2), 256>>>(a3_p, w3_p, bih1, xp_p, MM, GG, 3072);
    init_kernel<<<64, 256>>>();
    recur_tc_kernel<<<128, 256, sm_tc>>>(xp_p, whh1, bhh1, nullptr, 1);

    // ---- head ----
    mlp1_kernel<<<(BB * 128 * 32) / 256, 256>>>(w1, b1);
    mlp2_kernel<<<1, 128>>>(w2, b2, (float*)d_out);
}

// round 5
// speedup vs baseline: 2.7546x; 1.1287x over previous
#include <cuda_runtime.h>
#include <cuda_bf16.h>
#include <math.h>

#define BB 64
#define TT 256
#define EE 300
#define HH 512
#define GG 1536               // 3*H
#define MM (BB*TT)            // 16384

// ---------------- scratch (static device allocations only) ----------------
__device__ __align__(256) float g_e[MM * EE];            // embedded input  [B*T, 300]
__device__ __align__(256) float g_xp[2 * MM * GG];       // input projections [dir][B*T, 1536]
__device__ __align__(256) float g_y0[MM * 2 * HH];       // layer0 output [B*T, 1024]
__device__ __align__(256) __nv_bfloat16 g_hA[2][2][BB][1024]; // h split [buf][dir][b][hi|lo]
__device__ __align__(256) float g_pooled[BB * 2 * HH];   // maxpool [B, 1024]
__device__ __align__(256) float g_hid[BB * 128];         // mlp hidden
__device__ __align__(256) __nv_bfloat16 g_a3[MM * 3 * 1024];        // split A [M, 3*Kp]
__device__ __align__(256) __nv_bfloat16 g_w3[2 * GG * 3 * 1024];    // split W [2N, 3*Kp]
__device__ unsigned g_bar4[4];

// ---------------- init: zero hidden split buffers + barriers ----------------
__global__ void init_kernel() {
    const int n = 2 * 2 * BB * 1024 / 2;   // as uint count
    unsigned* p = reinterpret_cast<unsigned*>(&g_hA[0][0][0][0]);
    for (int i = blockIdx.x * blockDim.x + threadIdx.x; i < n; i += gridDim.x * blockDim.x)
        p[i] = 0u;
    if (blockIdx.x == 0 && threadIdx.x < 4) g_bar4[threadIdx.x] = 0u;
}

// ---------------- embedding gather ----------------
__global__ void embed_kernel(const int* __restrict__ x, const float* __restrict__ emb) {
    const int tok = blockIdx.x;
    const int row = x[tok];
    const float4* src = reinterpret_cast<const float4*>(emb + (size_t)row * EE);
    float4* dst = reinterpret_cast<float4*>(g_e + (size_t)tok * EE);
    for (int i = threadIdx.x; i < EE / 4; i += blockDim.x) dst[i] = src[i];
}

// ---------------- bf16 split conversion ----------------
// mode 0 (A): slabs = [hi | hi | lo];  mode 1 (W): slabs = [hi | lo | hi]
__global__ void conv_split_kernel(const float* __restrict__ src, __nv_bfloat16* __restrict__ dst,
                                  int rows, int Ksrc, int Kp, int mode) {
    const long i = (long)blockIdx.x * blockDim.x + threadIdx.x;   // pair index
    const long total = (long)rows * (Kp / 2);
    if (i >= total) return;
    const int m  = (int)(i / (Kp / 2));
    const int k0 = (int)(i % (Kp / 2)) * 2;
    const float v0 = (k0     < Ksrc) ? src[(size_t)m * Ksrc + k0]     : 0.f;
    const float v1 = (k0 + 1 < Ksrc) ? src[(size_t)m * Ksrc + k0 + 1] : 0.f;
    const __nv_bfloat16 h0 = __float2bfloat16(v0), h1 = __float2bfloat16(v1);
    const __nv_bfloat16 l0 = __float2bfloat16(v0 - __bfloat162float(h0));
    const __nv_bfloat16 l1 = __float2bfloat16(v1 - __bfloat162float(h1));
    const __nv_bfloat162 hh = __halves2bfloat162(h0, h1);
    const __nv_bfloat162 ll = __halves2bfloat162(l0, l1);
    __nv_bfloat162* d = reinterpret_cast<__nv_bfloat162*>(dst + (size_t)m * 3 * Kp);
    const int p = k0 >> 1, s = Kp >> 1;
    if (mode == 0) { d[p] = hh; d[p + s] = hh; d[p + 2 * s] = ll; }
    else           { d[p] = hh; d[p + s] = ll; d[p + 2 * s] = hh; }
}

// ---------------- bf16 tensor-core GEMM with fused bias ----------------
#define PKH 40
__global__ void __launch_bounds__(256, 2) bgemm_kernel(
    const __nv_bfloat16* __restrict__ A,   // [M, K3]
    const __nv_bfloat16* __restrict__ W,   // [2][N, K3]
    const float* __restrict__ bias,        // [2][N]
    float* __restrict__ C,                 // [2][M, N]
    int M, int N, int K3)
{
    __shared__ __align__(16) __nv_bfloat16 As[2][128 * PKH];
    __shared__ __align__(16) __nv_bfloat16 Bs[2][128 * PKH];

    const int z = blockIdx.z;
    W    += (size_t)z * N * K3;
    bias += (size_t)z * N;
    C    += (size_t)z * M * N;

    const int m0 = blockIdx.y * 128, n0 = blockIdx.x * 128;
    const int tid = threadIdx.x;
    const int warp = tid >> 5, lane = tid & 31;
    const int wm = warp >> 2, wn = warp & 3;

    float c[4][4][4];
#pragma unroll
    for (int mi = 0; mi < 4; mi++)
#pragma unroll
        for (int ni = 0; ni < 4; ni++)
#pragma unroll
            for (int q = 0; q < 4; q++) c[mi][ni][q] = 0.f;

    const int lrow = tid >> 2;
    const int lcol = (tid & 3) * 8;

    {
        const uint4 a0 = *reinterpret_cast<const uint4*>(A + (size_t)(m0 + lrow) * K3 + lcol);
        const uint4 a1 = *reinterpret_cast<const uint4*>(A + (size_t)(m0 + lrow + 64) * K3 + lcol);
        const uint4 b0 = *reinterpret_cast<const uint4*>(W + (size_t)(n0 + lrow) * K3 + lcol);
        const uint4 b1 = *reinterpret_cast<const uint4*>(W + (size_t)(n0 + lrow + 64) * K3 + lcol);
        *reinterpret_cast<uint4*>(&As[0][lrow * PKH + lcol]) = a0;
        *reinterpret_cast<uint4*>(&As[0][(lrow + 64) * PKH + lcol]) = a1;
        *reinterpret_cast<uint4*>(&Bs[0][lrow * PKH + lcol]) = b0;
        *reinterpret_cast<uint4*>(&Bs[0][(lrow + 64) * PKH + lcol]) = b1;
    }
    __syncthreads();

    const int nk = K3 / 32;
    uint4 pa0, pa1, pb0, pb1;

    for (int kt = 0; kt < nk; kt++) {
        const int cur = kt & 1;
        if (kt + 1 < nk) {
            const int kg = (kt + 1) * 32 + lcol;
            pa0 = *reinterpret_cast<const uint4*>(A + (size_t)(m0 + lrow) * K3 + kg);
            pa1 = *reinterpret_cast<const uint4*>(A + (size_t)(m0 + lrow + 64) * K3 + kg);
            pb0 = *reinterpret_cast<const uint4*>(W + (size_t)(n0 + lrow) * K3 + kg);
            pb1 = *reinterpret_cast<const uint4*>(W + (size_t)(n0 + lrow + 64) * K3 + kg);
        }

        const unsigned abase = (unsigned)__cvta_generic_to_shared(&As[cur][0]);
        const unsigned bbase = (unsigned)__cvta_generic_to_shared(&Bs[cur][0]);

#pragma unroll
        for (int kk = 0; kk < 32; kk += 16) {
            unsigned a[4][4], b[4][2];
#pragma unroll
            for (int mi = 0; mi < 4; mi++) {
                const unsigned ad = abase +
                    (((wm * 64 + mi * 16 + (lane & 15)) * PKH + kk + (lane >> 4) * 8) << 1);
                asm volatile("ldmatrix.sync.aligned.m8n8.x4.shared.b16 {%0,%1,%2,%3}, [%4];"
                    : "=r"(a[mi][0]), "=r"(a[mi][1]), "=r"(a[mi][2]), "=r"(a[mi][3]) : "r"(ad));
            }
#pragma unroll
            for (int nj = 0; nj < 2; nj++) {
                const int g = lane >> 3, rr = lane & 7;
                const unsigned bd = bbase +
                    (((wn * 32 + nj * 16 + (g >> 1) * 8 + rr) * PKH + kk + (g & 1) * 8) << 1);
                asm volatile("ldmatrix.sync.aligned.m8n8.x4.shared.b16 {%0,%1,%2,%3}, [%4];"
                    : "=r"(b[nj * 2][0]), "=r"(b[nj * 2][1]),
                      "=r"(b[nj * 2 + 1][0]), "=r"(b[nj * 2 + 1][1]) : "r"(bd));
            }
#pragma unroll
            for (int mi = 0; mi < 4; mi++)
#pragma unroll
                for (int ni = 0; ni < 4; ni++)
                    asm volatile(
                        "mma.sync.aligned.m16n8k16.row.col.f32.bf16.bf16.f32 "
                        "{%0,%1,%2,%3}, {%4,%5,%6,%7}, {%8,%9}, {%0,%1,%2,%3};"
                        : "+f"(c[mi][ni][0]), "+f"(c[mi][ni][1]),
                          "+f"(c[mi][ni][2]), "+f"(c[mi][ni][3])
                        : "r"(a[mi][0]), "r"(a[mi][1]), "r"(a[mi][2]), "r"(a[mi][3]),
                          "r"(b[ni][0]), "r"(b[ni][1]));
        }

        if (kt + 1 < nk) {
            const int nxt = cur ^ 1;
            *reinterpret_cast<uint4*>(&As[nxt][lrow * PKH + lcol]) = pa0;
            *reinterpret_cast<uint4*>(&As[nxt][(lrow + 64) * PKH + lcol]) = pa1;
            *reinterpret_cast<uint4*>(&Bs[nxt][lrow * PKH + lcol]) = pb0;
            *reinterpret_cast<uint4*>(&Bs[nxt][(lrow + 64) * PKH + lcol]) = pb1;
            __syncthreads();
        }
    }

#pragma unroll
    for (int mi = 0; mi < 4; mi++) {
        const int row = m0 + wm * 64 + mi * 16 + (lane >> 2);
#pragma unroll
        for (int ni = 0; ni < 4; ni++) {
            const int col = n0 + wn * 32 + ni * 8 + (lane & 3) * 2;
            const float bx = bias[col], by = bias[col + 1];
            float2 v0 = make_float2(c[mi][ni][0] + bx, c[mi][ni][1] + by);
            float2 v1 = make_float2(c[mi][ni][2] + bx, c[mi][ni][3] + by);
            *reinterpret_cast<float2*>(&C[(size_t)row * N + col]) = v0;
            *reinterpret_cast<float2*>(&C[(size_t)(row + 8) * N + col]) = v1;
        }
    }
}

// ---------------- group barrier (release/acquire, monotonic counter) ----------------
__device__ __forceinline__ void group_barrier(unsigned* ctr, unsigned& tgt, unsigned nctas) {
    __syncthreads();
    if (threadIdx.x == 0) {
        tgt += nctas;
        const unsigned t = tgt;
        unsigned prev;
        asm volatile("atom.acq_rel.gpu.global.add.u32 %0, [%1], 1;"
                     : "=r"(prev) : "l"(ctr) : "memory");
        if (prev + 1u != t) {
            unsigned v;
            do {
                asm volatile("ld.acquire.gpu.global.u32 %0, [%1];"
                             : "=r"(v) : "l"(ctr) : "memory");
            } while (v < t);
        }
    }
    __syncthreads();
}

// ---------------- tensor-core persistent BiGRU recurrence ----------------
// 128 CTAs: dir = cta>>6, ks = (cta&63)>>1 (16 k-cols), bg = cta&1 (32 batches).
// 4 independent sync groups (dir,bg) of 32 CTAs.
// Per step per CTA: gh[32 b x 48 g] = h3[32 x 1024] x W3slice (3-term bf16 split).
#define PA 1032   // A smem pitch (halves)
#define PW 520    // W smem pitch (halves)
#define SGP 49    // sgh pitch
__global__ void __launch_bounds__(256, 1) recur_tc_kernel(
    const float* __restrict__ xp,    // [dir][B*T, 1536] (includes b_ih)
    const float* __restrict__ w_hh,  // [2][1536][512]
    const float* __restrict__ b_hh,  // [2][1536]
    float* __restrict__ y,           // [B*T, 1024] or nullptr
    int do_pool)
{
    extern __shared__ char smraw[];
    __nv_bfloat16* sWhi = reinterpret_cast<__nv_bfloat16*>(smraw);   // [48][PW]
    __nv_bfloat16* sWlo = sWhi + 48 * PW;                             // [48][PW]
    __nv_bfloat16* sA   = sWlo + 48 * PW;                             // [32][PA]
    float* sgh   = reinterpret_cast<float*>(sA + 32 * PA);            // [32][SGP]
    float* sred  = sgh + 32 * SGP;                                    // [4*32][13]
    float* shsl  = sred + 4 * 32 * 13;                                // [16][33]
    float* sbias = shsl + 16 * 33;                                    // [48]

    const int cta = blockIdx.x;
    const int dir = cta >> 6;
    const int ks  = (cta & 63) >> 1;
    const int bg  = cta & 1;
    const int k0  = ks * 16;
    const int tid = threadIdx.x;
    const int warp = tid >> 5, lane = tid & 31;
    const int kh = warp >> 2;          // k-half
    const int wm = (warp >> 1) & 1;    // m-tile (16 batches)
    const int wn = warp & 1;           // n-half (24 gate rows)
    unsigned* bar = &g_bar4[dir * 2 + bg];

    // ---- load + split W_hh slice: row jj = g*16+kc -> global row g*512 + k0 + kc
    {
        const float* wsrc = w_hh + (size_t)dir * GG * HH;
        for (int idx = tid; idx < 48 * 128; idx += 256) {
            const int jj = idx >> 7;
            const int q  = (idx & 127) * 4;
            const int grow = (jj >> 4) * HH + k0 + (jj & 15);
            const float4 v = *reinterpret_cast<const float4*>(&wsrc[(size_t)grow * HH + q]);
            const __nv_bfloat16 h0 = __float2bfloat16(v.x), h1 = __float2bfloat16(v.y);
            const __nv_bfloat16 h2 = __float2bfloat16(v.z), h3 = __float2bfloat16(v.w);
            const __nv_bfloat16 l0 = __float2bfloat16(v.x - __bfloat162float(h0));
            const __nv_bfloat16 l1 = __float2bfloat16(v.y - __bfloat162float(h1));
            const __nv_bfloat16 l2 = __float2bfloat16(v.z - __bfloat162float(h2));
            const __nv_bfloat16 l3 = __float2bfloat16(v.w - __bfloat162float(h3));
            __nv_bfloat162* dh = reinterpret_cast<__nv_bfloat162*>(sWhi + jj * PW + q);
            __nv_bfloat162* dl = reinterpret_cast<__nv_bfloat162*>(sWlo + jj * PW + q);
            dh[0] = __halves2bfloat162(h0, h1); dh[1] = __halves2bfloat162(h2, h3);
            dl[0] = __halves2bfloat162(l0, l1); dl[1] = __halves2bfloat162(l2, l3);
        }
        if (tid < 48)
            sbias[tid] = b_hh[dir * GG + (tid >> 4) * HH + k0 + (tid & 15)];
        for (int i = tid; i < 16 * 33; i += 256) shsl[i] = 0.f;
    }
    __syncthreads();

    const int b_ep = tid >> 3;               // epilogue batch (0..31)
    const int kc2  = (tid & 7) * 2;          // epilogue k pair base (0..14)
    float mx[2] = {-1e30f, -1e30f};
    unsigned bar_tgt = 0;

    const unsigned sAb  = (unsigned)__cvta_generic_to_shared(sA);
    const unsigned sWhb = (unsigned)__cvta_generic_to_shared(sWhi);
    const unsigned sWlb = (unsigned)__cvta_generic_to_shared(sWlo);

    for (int s = 0; s < TT; s++) {
        const int t = dir ? (TT - 1 - s) : s;
        const int p = s & 1;

        // ---- prefetch xp epilogue operands (independent of h)
        const size_t xbase = ((size_t)(dir * BB + bg * 32 + b_ep) * TT + t) * GG + k0 + kc2;
        const float2 xr = __ldg(reinterpret_cast<const float2*>(xp + xbase));
        const float2 xz = __ldg(reinterpret_cast<const float2*>(xp + xbase + HH));
        const float2 xn = __ldg(reinterpret_cast<const float2*>(xp + xbase + 2 * HH));

        // ---- issue h load: 4 x 16KB cp.async chunks (hi cols first)
        {
            const __nv_bfloat16* hsrc = &g_hA[p][dir][bg * 32][0];
#pragma unroll
            for (int c = 0; c < 4; c++) {
#pragma unroll
                for (int it = 0; it < 4; it++) {
                    const int idx = it * 256 + tid;
                    const int row = idx >> 5, seg = idx & 31;
                    const int col = c * 256 + seg * 8;
                    const unsigned d = sAb + (unsigned)((row * PA + col) << 1);
                    const __nv_bfloat16* gp = hsrc + row * 1024 + col;
                    asm volatile("cp.async.cg.shared.global [%0], [%1], 16;"
                                 :: "r"(d), "l"(gp) : "memory");
                }
                asm volatile("cp.async.commit_group;" ::: "memory");
            }
        }

        float c0[4] = {0.f, 0.f, 0.f, 0.f};
        float c1[4] = {0.f, 0.f, 0.f, 0.f};
        float c2[4] = {0.f, 0.f, 0.f, 0.f};

#define MMA_PASS(AOFF, WSB)                                                          \
        for (int kk = kh * 256; kk < kh * 256 + 256; kk += 16) {                     \
            unsigned a0, a1, a2, a3, b00, b01, b10, b11, b20, b21;                   \
            const unsigned ad = sAb +                                                \
                ((((wm * 16 + (lane & 15)) * PA) + (AOFF) + kk + (lane >> 4) * 8) << 1); \
            asm volatile("ldmatrix.sync.aligned.m8n8.x4.shared.b16 {%0,%1,%2,%3}, [%4];" \
                : "=r"(a0), "=r"(a1), "=r"(a2), "=r"(a3) : "r"(ad));                 \
            const int g_ = lane >> 3, rr_ = lane & 7;                                \
            const unsigned bd = (WSB) +                                              \
                (((wn * 24 + (g_ >> 1) * 8 + rr_) * PW + kk + (g_ & 1) * 8) << 1);   \
            asm volatile("ldmatrix.sync.aligned.m8n8.x4.shared.b16 {%0,%1,%2,%3}, [%4];" \
                : "=r"(b00), "=r"(b01), "=r"(b10), "=r"(b11) : "r"(bd));             \
            const unsigned bd2 = (WSB) +                                             \
                (((wn * 24 + 16 + rr_) * PW + kk + ((lane >> 3) & 1) * 8) << 1);     \
            asm volatile("ldmatrix.sync.aligned.m8n8.x2.shared.b16 {%0,%1}, [%2];"   \
                : "=r"(b20), "=r"(b21) : "r"(bd2));                                  \
            asm volatile("mma.sync.aligned.m16n8k16.row.col.f32.bf16.bf16.f32 "      \
                "{%0,%1,%2,%3}, {%4,%5,%6,%7}, {%8,%9}, {%0,%1,%2,%3};"              \
                : "+f"(c0[0]), "+f"(c0[1]), "+f"(c0[2]), "+f"(c0[3])                 \
                : "r"(a0), "r"(a1), "r"(a2), "r"(a3), "r"(b00), "r"(b01));           \
            asm volatile("mma.sync.aligned.m16n8k16.row.col.f32.bf16.bf16.f32 "      \
                "{%0,%1,%2,%3}, {%4,%5,%6,%7}, {%8,%9}, {%0,%1,%2,%3};"              \
                : "+f"(c1[0]), "+f"(c1[1]), "+f"(c1[2]), "+f"(c1[3])                 \
                : "r"(a0), "r"(a1), "r"(a2), "r"(a3), "r"(b10), "r"(b11));           \
            asm volatile("mma.sync.aligned.m16n8k16.row.col.f32.bf16.bf16.f32 "      \
                "{%0,%1,%2,%3}, {%4,%5,%6,%7}, {%8,%9}, {%0,%1,%2,%3};"              \
                : "+f"(c2[0]), "+f"(c2[1]), "+f"(c2[2]), "+f"(c2[3])                 \
                : "r"(a0), "r"(a1), "r"(a2), "r"(a3), "r"(b20), "r"(b21));           \
        }

        // hi chunks (0,1) ready when 2 groups still pending
        asm volatile("cp.async.wait_group 2;" ::: "memory");
        __syncthreads();
        MMA_PASS(0,   sWhb)   // hi * Whi
        MMA_PASS(0,   sWlb)   // hi * Wlo
        asm volatile("cp.async.wait_group 0;" ::: "memory");
        __syncthreads();
        MMA_PASS(512, sWhb)   // lo * Whi

        // ---- reduce k-halves
        if (kh == 1) {
            float* rp = sred + (size_t)(((warp - 4) << 5) + lane) * 13;
#pragma unroll
            for (int q = 0; q < 4; q++) {
                rp[q] = c0[q]; rp[4 + q] = c1[q]; rp[8 + q] = c2[q];
            }
        }
        __syncthreads();
        if (kh == 0) {
            const float* rp = sred + (size_t)((warp << 5) + lane) * 13;
#pragma unroll
            for (int q = 0; q < 4; q++) {
                c0[q] += rp[q]; c1[q] += rp[4 + q]; c2[q] += rp[8 + q];
            }
            // scatter: rows = batch, cols = gate-row jj (0..47)
#pragma unroll
            for (int q = 0; q < 4; q++) {
                const int row = wm * 16 + (lane >> 2) + (q >> 1) * 8;
                const int col = wn * 24 + (lane & 3) * 2 + (q & 1);
                sgh[row * SGP + col]      = c0[q];
                sgh[row * SGP + 8 + col]  = c1[q];
                sgh[row * SGP + 16 + col] = c2[q];
            }
        }
        __syncthreads();

        // ---- epilogue: 2 cells per thread (b_ep, kc2..kc2+1)
        {
            float hv[2];
#pragma unroll
            for (int j = 0; j < 2; j++) {
                const int kc = kc2 + j;
                const float gr = sgh[b_ep * SGP + kc]      + sbias[kc];
                const float gz = sgh[b_ep * SGP + 16 + kc] + sbias[16 + kc];
                const float gn = sgh[b_ep * SGP + 32 + kc] + sbias[32 + kc];
                const float xrv = j ? xr.y : xr.x;
                const float xzv = j ? xz.y : xz.x;
                const float xnv = j ? xn.y : xn.x;
                const float rg = 1.f / (1.f + expf(-(xrv + gr)));
                const float zg = 1.f / (1.f + expf(-(xzv + gz)));
                const float ng = tanhf(xnv + rg * gn);
                const float hp = shsl[kc * 33 + b_ep];
                hv[j] = (1.f - zg) * ng + zg * hp;
                shsl[kc * 33 + b_ep] = hv[j];
                if (do_pool) mx[j] = fmaxf(mx[j], hv[j]);
            }
            const __nv_bfloat16 h0 = __float2bfloat16(hv[0]);
            const __nv_bfloat16 h1 = __float2bfloat16(hv[1]);
            const __nv_bfloat16 l0 = __float2bfloat16(hv[0] - __bfloat162float(h0));
            const __nv_bfloat16 l1 = __float2bfloat16(hv[1] - __bfloat162float(h1));
            const __nv_bfloat162 hp2 = __halves2bfloat162(h0, h1);
            const __nv_bfloat162 lp2 = __halves2bfloat162(l0, l1);
            __nv_bfloat16* dst = &g_hA[1 - p][dir][bg * 32 + b_ep][k0 + kc2];
            __stcg(reinterpret_cast<unsigned*>(dst),
                   *reinterpret_cast<const unsigned*>(&hp2));
            __stcg(reinterpret_cast<unsigned*>(dst + 512),
                   *reinterpret_cast<const unsigned*>(&lp2));
            if (y) {
                float2 yv = make_float2(hv[0], hv[1]);
                *reinterpret_cast<float2*>(
                    &y[((size_t)(bg * 32 + b_ep) * TT + t) * (2 * HH) + dir * HH + k0 + kc2]) = yv;
            }
        }
        group_barrier(bar, bar_tgt, 32u);
    }

    if (do_pool) {
        g_pooled[(size_t)(bg * 32 + b_ep) * (2 * HH) + dir * HH + k0 + kc2]     = mx[0];
        g_pooled[(size_t)(bg * 32 + b_ep) * (2 * HH) + dir * HH + k0 + kc2 + 1] = mx[1];
    }
}

// ---------------- classifier head ----------------
__global__ void mlp1_kernel(const float* __restrict__ w1, const float* __restrict__ b1) {
    const int warp = (blockIdx.x * blockDim.x + threadIdx.x) >> 5;
    const int lane = threadIdx.x & 31;
    if (warp >= BB * 128) return;
    const int b = warp >> 7, j = warp & 127;
    const float* p = g_pooled + (size_t)b * 2 * HH;
    const float* w = w1 + (size_t)j * 2 * HH;
    float s = 0.f;
    for (int k = lane; k < 2 * HH; k += 32) s = fmaf(p[k], w[k], s);
#pragma unroll
    for (int o = 16; o; o >>= 1) s += __shfl_xor_sync(0xffffffffu, s, o);
    if (lane == 0) g_hid[b * 128 + j] = fmaxf(s + b1[j], 0.f);
}

__global__ void mlp2_kernel(const float* __restrict__ w2, const float* __restrict__ b2,
                            float* __restrict__ out) {
    const int t = threadIdx.x;
    if (t < BB * 2) {
        const int b = t >> 1, c = t & 1;
        float s = b2[c];
        const float* h = g_hid + b * 128;
        const float* w = w2 + c * 128;
        for (int k = 0; k < 128; k++) s = fmaf(h[k], w[k], s);
        out[t] = s;
    }
}

// ---------------- launch ----------------
extern "C" void kernel_launch(void* const* d_in, const int* in_sizes, int n_in,
                              void* d_out, int out_size) {
    const int*   x    = (const int*)d_in[0];
    const float* emb  = (const float*)d_in[1];
    const float* wih0 = (const float*)d_in[2];
    const float* whh0 = (const float*)d_in[3];
    const float* bih0 = (const float*)d_in[4];
    const float* bhh0 = (const float*)d_in[5];
    const float* wih1 = (const float*)d_in[6];
    const float* whh1 = (const float*)d_in[7];
    const float* bih1 = (const float*)d_in[8];
    const float* bhh1 = (const float*)d_in[9];
    const float* w1   = (const float*)d_in[10];
    const float* b1   = (const float*)d_in[11];
    const float* w2   = (const float*)d_in[12];
    const float* b2   = (const float*)d_in[13];

    float *e_p = nullptr, *xp_p = nullptr, *y0_p = nullptr;
    __nv_bfloat16 *a3_p = nullptr, *w3_p = nullptr;
    cudaGetSymbolAddress((void**)&e_p,  g_e);
    cudaGetSymbolAddress((void**)&xp_p, g_xp);
    cudaGetSymbolAddress((void**)&y0_p, g_y0);
    cudaGetSymbolAddress((void**)&a3_p, g_a3);
    cudaGetSymbolAddress((void**)&w3_p, g_w3);

    const size_t sm_tc = (size_t)(2 * 48 * PW + 32 * PA) * sizeof(__nv_bfloat16)
                       + (size_t)(32 * SGP + 4 * 32 * 13 + 16 * 33 + 48) * sizeof(float);
    cudaFuncSetAttribute(recur_tc_kernel, cudaFuncAttributeMaxDynamicSharedMemorySize, (int)sm_tc);

    // ---- layer 0 ----
    init_kernel<<<64, 256>>>();
    embed_kernel<<<MM, 128>>>(x, emb);
    {
        const long pa = (long)MM * (320 / 2);
        conv_split_kernel<<<(unsigned)((pa + 255) / 256), 256>>>(e_p, a3_p, MM, EE, 320, 0);
        const long pw = (long)(2 * GG) * (320 / 2);
        conv_split_kernel<<<(unsigned)((pw + 255) / 256), 256>>>(wih0, w3_p, 2 * GG, EE, 320, 1);
    }
    bgemm_kernel<<<dim3(GG / 128, MM / 128, 2), 256>>>(a3_p, w3_p, bih0, xp_p, MM, GG, 960);
    recur_tc_kernel<<<128, 256, sm_tc>>>(xp_p, whh0, bhh0, y0_p, 0);

    // ---- layer 1 ----
    {
        const long pa = (long)MM * (1024 / 2);
        conv_split_kernel<<<(unsigned)((pa + 255) / 256), 256>>>(y0_p, a3_p, MM, 2 * HH, 1024, 0);
        const long pw = (long)(2 * GG) * (1024 / 2);
        conv_split_kernel<<<(unsigned)((pw + 255) / 256), 256>>>(wih1, w3_p, 2 * GG, 2 * HH, 1024, 1);
    }
    bgemm_kernel<<<dim3(GG / 128, MM / 128, 2), 256>>>(a3_p, w3_p, bih1, xp_p, MM, GG, 3072);
    init_kernel<<<64, 256>>>();
    recur_tc_kernel<<<128, 256, sm_tc>>>(xp_p, whh1, bhh1, nullptr, 1);

    // ---- head ----
    mlp1_kernel<<<(BB * 128 * 32) / 256, 256>>>(w1, b1);
    mlp2_kernel<<<1, 128>>>(w2, b2, (float*)d_out);
}

// round 6
// speedup vs baseline: 2.8500x; 1.0346x over previous
#include <cuda_runtime.h>
#include <cuda_bf16.h>
#include <math.h>

#define BB 64
#define TT 256
#define EE 300
#define HH 512
#define GG 1536               // 3*H
#define MM (BB*TT)            // 16384

// ---------------- scratch (static device allocations only) ----------------
__device__ __align__(256) float g_e[MM * EE];            // embedded input  [B*T, 300]
__device__ __align__(256) float g_xp[2 * MM * GG];       // input projections [dir][B*T, 1536]
__device__ __align__(256) __nv_bfloat16 g_hA[2][2][BB][1024]; // h split [buf][dir][b][hi|lo]
__device__ __align__(256) float g_pooled[BB * 2 * HH];   // maxpool [B, 1024]
__device__ __align__(256) float g_hid[BB * 128];         // mlp hidden
__device__ __align__(256) __nv_bfloat16 g_a3[MM * 3 * 1024];        // split A [M, 3*Kp]
__device__ __align__(256) __nv_bfloat16 g_w3[2 * GG * 3 * 1024];    // split W [2N, 3*Kp]
__device__ unsigned g_bar4[4];

// ---------------- init ----------------
__global__ void init_kernel() {
    const int n = 2 * 2 * BB * 1024 / 2;
    unsigned* p = reinterpret_cast<unsigned*>(&g_hA[0][0][0][0]);
    for (int i = blockIdx.x * blockDim.x + threadIdx.x; i < n; i += gridDim.x * blockDim.x)
        p[i] = 0u;
    if (blockIdx.x == 0 && threadIdx.x < 4) g_bar4[threadIdx.x] = 0u;
}

// ---------------- embedding gather ----------------
__global__ void embed_kernel(const int* __restrict__ x, const float* __restrict__ emb) {
    const int tok = blockIdx.x;
    const int row = x[tok];
    const float4* src = reinterpret_cast<const float4*>(emb + (size_t)row * EE);
    float4* dst = reinterpret_cast<float4*>(g_e + (size_t)tok * EE);
    for (int i = threadIdx.x; i < EE / 4; i += blockDim.x) dst[i] = src[i];
}

// ---------------- bf16 split conversion ----------------
__global__ void conv_split_kernel(const float* __restrict__ src, __nv_bfloat16* __restrict__ dst,
                                  int rows, int Ksrc, int Kp, int mode) {
    const long i = (long)blockIdx.x * blockDim.x + threadIdx.x;
    const long total = (long)rows * (Kp / 2);
    if (i >= total) return;
    const int m  = (int)(i / (Kp / 2));
    const int k0 = (int)(i % (Kp / 2)) * 2;
    const float v0 = (k0     < Ksrc) ? src[(size_t)m * Ksrc + k0]     : 0.f;
    const float v1 = (k0 + 1 < Ksrc) ? src[(size_t)m * Ksrc + k0 + 1] : 0.f;
    const __nv_bfloat16 h0 = __float2bfloat16(v0), h1 = __float2bfloat16(v1);
    const __nv_bfloat16 l0 = __float2bfloat16(v0 - __bfloat162float(h0));
    const __nv_bfloat16 l1 = __float2bfloat16(v1 - __bfloat162float(h1));
    const __nv_bfloat162 hh = __halves2bfloat162(h0, h1);
    const __nv_bfloat162 ll = __halves2bfloat162(l0, l1);
    __nv_bfloat162* d = reinterpret_cast<__nv_bfloat162*>(dst + (size_t)m * 3 * Kp);
    const int p = k0 >> 1, s = Kp >> 1;
    if (mode == 0) { d[p] = hh; d[p + s] = hh; d[p + 2 * s] = ll; }
    else           { d[p] = hh; d[p + s] = ll; d[p + 2 * s] = hh; }
}

// ---------------- bf16 tensor-core GEMM with fused bias ----------------
#define PKH 40
__global__ void __launch_bounds__(256, 2) bgemm_kernel(
    const __nv_bfloat16* __restrict__ A, const __nv_bfloat16* __restrict__ W,
    const float* __restrict__ bias, float* __restrict__ C, int M, int N, int K3)
{
    __shared__ __align__(16) __nv_bfloat16 As[2][128 * PKH];
    __shared__ __align__(16) __nv_bfloat16 Bs[2][128 * PKH];

    const int z = blockIdx.z;
    W    += (size_t)z * N * K3;
    bias += (size_t)z * N;
    C    += (size_t)z * M * N;

    const int m0 = blockIdx.y * 128, n0 = blockIdx.x * 128;
    const int tid = threadIdx.x;
    const int warp = tid >> 5, lane = tid & 31;
    const int wm = warp >> 2, wn = warp & 3;

    float c[4][4][4];
#pragma unroll
    for (int mi = 0; mi < 4; mi++)
#pragma unroll
        for (int ni = 0; ni < 4; ni++)
#pragma unroll
            for (int q = 0; q < 4; q++) c[mi][ni][q] = 0.f;

    const int lrow = tid >> 2;
    const int lcol = (tid & 3) * 8;

    {
        const uint4 a0 = *reinterpret_cast<const uint4*>(A + (size_t)(m0 + lrow) * K3 + lcol);
        const uint4 a1 = *reinterpret_cast<const uint4*>(A + (size_t)(m0 + lrow + 64) * K3 + lcol);
        const uint4 b0 = *reinterpret_cast<const uint4*>(W + (size_t)(n0 + lrow) * K3 + lcol);
        const uint4 b1 = *reinterpret_cast<const uint4*>(W + (size_t)(n0 + lrow + 64) * K3 + lcol);
        *reinterpret_cast<uint4*>(&As[0][lrow * PKH + lcol]) = a0;
        *reinterpret_cast<uint4*>(&As[0][(lrow + 64) * PKH + lcol]) = a1;
        *reinterpret_cast<uint4*>(&Bs[0][lrow * PKH + lcol]) = b0;
        *reinterpret_cast<uint4*>(&Bs[0][(lrow + 64) * PKH + lcol]) = b1;
    }
    __syncthreads();

    const int nk = K3 / 32;
    uint4 pa0, pa1, pb0, pb1;

    for (int kt = 0; kt < nk; kt++) {
        const int cur = kt & 1;
        if (kt + 1 < nk) {
            const int kg = (kt + 1) * 32 + lcol;
            pa0 = *reinterpret_cast<const uint4*>(A + (size_t)(m0 + lrow) * K3 + kg);
            pa1 = *reinterpret_cast<const uint4*>(A + (size_t)(m0 + lrow + 64) * K3 + kg);
            pb0 = *reinterpret_cast<const uint4*>(W + (size_t)(n0 + lrow) * K3 + kg);
            pb1 = *reinterpret_cast<const uint4*>(W + (size_t)(n0 + lrow + 64) * K3 + kg);
        }

        const unsigned abase = (unsigned)__cvta_generic_to_shared(&As[cur][0]);
        const unsigned bbase = (unsigned)__cvta_generic_to_shared(&Bs[cur][0]);

#pragma unroll
        for (int kk = 0; kk < 32; kk += 16) {
            unsigned a[4][4], b[4][2];
#pragma unroll
            for (int mi = 0; mi < 4; mi++) {
                const unsigned ad = abase +
                    (((wm * 64 + mi * 16 + (lane & 15)) * PKH + kk + (lane >> 4) * 8) << 1);
                asm volatile("ldmatrix.sync.aligned.m8n8.x4.shared.b16 {%0,%1,%2,%3}, [%4];"
                    : "=r"(a[mi][0]), "=r"(a[mi][1]), "=r"(a[mi][2]), "=r"(a[mi][3]) : "r"(ad));
            }
#pragma unroll
            for (int nj = 0; nj < 2; nj++) {
                const int g = lane >> 3, rr = lane & 7;
                const unsigned bd = bbase +
                    (((wn * 32 + nj * 16 + (g >> 1) * 8 + rr) * PKH + kk + (g & 1) * 8) << 1);
                asm volatile("ldmatrix.sync.aligned.m8n8.x4.shared.b16 {%0,%1,%2,%3}, [%4];"
                    : "=r"(b[nj * 2][0]), "=r"(b[nj * 2][1]),
                      "=r"(b[nj * 2 + 1][0]), "=r"(b[nj * 2 + 1][1]) : "r"(bd));
            }
#pragma unroll
            for (int mi = 0; mi < 4; mi++)
#pragma unroll
                for (int ni = 0; ni < 4; ni++)
                    asm volatile(
                        "mma.sync.aligned.m16n8k16.row.col.f32.bf16.bf16.f32 "
                        "{%0,%1,%2,%3}, {%4,%5,%6,%7}, {%8,%9}, {%0,%1,%2,%3};"
                        : "+f"(c[mi][ni][0]), "+f"(c[mi][ni][1]),
                          "+f"(c[mi][ni][2]), "+f"(c[mi][ni][3])
                        : "r"(a[mi][0]), "r"(a[mi][1]), "r"(a[mi][2]), "r"(a[mi][3]),
                          "r"(b[ni][0]), "r"(b[ni][1]));
        }

        if (kt + 1 < nk) {
            const int nxt = cur ^ 1;
            *reinterpret_cast<uint4*>(&As[nxt][lrow * PKH + lcol]) = pa0;
            *reinterpret_cast<uint4*>(&As[nxt][(lrow + 64) * PKH + lcol]) = pa1;
            *reinterpret_cast<uint4*>(&Bs[nxt][lrow * PKH + lcol]) = pb0;
            *reinterpret_cast<uint4*>(&Bs[nxt][(lrow + 64) * PKH + lcol]) = pb1;
            __syncthreads();
        }
    }

#pragma unroll
    for (int mi = 0; mi < 4; mi++) {
        const int row = m0 + wm * 64 + mi * 16 + (lane >> 2);
#pragma unroll
        for (int ni = 0; ni < 4; ni++) {
            const int col = n0 + wn * 32 + ni * 8 + (lane & 3) * 2;
            const float bx = bias[col], by = bias[col + 1];
            float2 v0 = make_float2(c[mi][ni][0] + bx, c[mi][ni][1] + by);
            float2 v1 = make_float2(c[mi][ni][2] + bx, c[mi][ni][3] + by);
            *reinterpret_cast<float2*>(&C[(size_t)row * N + col]) = v0;
            *reinterpret_cast<float2*>(&C[(size_t)(row + 8) * N + col]) = v1;
        }
    }
}

// ---------------- group barrier ----------------
__device__ __forceinline__ void group_barrier(unsigned* ctr, unsigned& tgt, unsigned nctas) {
    __syncthreads();
    if (threadIdx.x == 0) {
        tgt += nctas;
        const unsigned t = tgt;
        unsigned prev;
        asm volatile("atom.acq_rel.gpu.global.add.u32 %0, [%1], 1;"
                     : "=r"(prev) : "l"(ctr) : "memory");
        if (prev + 1u != t) {
            unsigned v;
            do {
                asm volatile("ld.acquire.gpu.global.u32 %0, [%1];"
                             : "=r"(v) : "l"(ctr) : "memory");
            } while (v < t);
        }
    }
    __syncthreads();
}

__device__ __forceinline__ float fast_sig(float x) {
    return __fdividef(1.f, 1.f + __expf(-x));
}
__device__ __forceinline__ float fast_tanh(float x) {
    return 1.f - __fdividef(2.f, __expf(2.f * x) + 1.f);
}

// ---------------- tensor-core persistent BiGRU recurrence ----------------
// 128 CTAs: dir = cta>>6, ks = (cta&63)>>1 (16 k-cols), bg = cta&1 (32 batches).
// W rows per wn-block: [r kc0-7 | z kc0-7 | n kc0-7] so epilogue is in-fragment.
#define PA 1032   // A smem pitch (halves)
#define PW 520    // W smem pitch (halves)
__global__ void __launch_bounds__(256, 1) recur_tc_kernel(
    const float* __restrict__ xp,    // [dir][B*T, 1536] (includes b_ih)
    const float* __restrict__ w_hh,  // [2][1536][512]
    const float* __restrict__ b_hh,  // [2][1536]
    __nv_bfloat16* __restrict__ a3,  // layer-1 split A out [M, 3*1024] or nullptr
    int do_pool)
{
    extern __shared__ char smraw[];
    __nv_bfloat16* sWhi = reinterpret_cast<__nv_bfloat16*>(smraw);   // [48][PW]
    __nv_bfloat16* sWlo = sWhi + 48 * PW;                             // [48][PW]
    __nv_bfloat16* sA   = sWlo + 48 * PW;                             // [32][PA]
    float* sred  = reinterpret_cast<float*>(sA + 32 * PA);            // [128][13]

    const int cta = blockIdx.x;
    const int dir = cta >> 6;
    const int ks  = (cta & 63) >> 1;
    const int bg  = cta & 1;
    const int k0  = ks * 16;
    const int tid = threadIdx.x;
    const int warp = tid >> 5, lane = tid & 31;
    const int kh = warp >> 2;          // k-half group
    const int wm = (warp >> 1) & 1;    // m-tile (16 batches)
    const int wn = warp & 1;           // n-half (kc 0-7 / 8-15)
    unsigned* bar = &g_bar4[dir * 2 + bg];

    // ---- load + split W_hh slice, rows ordered [blk(2)][gate(3)][kcl(8)]
    {
        const float* wsrc = w_hh + (size_t)dir * GG * HH;
        for (int idx = tid; idx < 48 * 128; idx += 256) {
            const int jj = idx >> 7;
            const int q  = (idx & 127) * 4;
            const int blk = jj / 24, within = jj % 24;
            const int gate = within >> 3, kcl = within & 7;
            const int grow = gate * HH + k0 + blk * 8 + kcl;
            const float4 v = *reinterpret_cast<const float4*>(&wsrc[(size_t)grow * HH + q]);
            const __nv_bfloat16 h0 = __float2bfloat16(v.x), h1 = __float2bfloat16(v.y);
            const __nv_bfloat16 h2 = __float2bfloat16(v.z), h3 = __float2bfloat16(v.w);
            const __nv_bfloat16 l0 = __float2bfloat16(v.x - __bfloat162float(h0));
            const __nv_bfloat16 l1 = __float2bfloat16(v.y - __bfloat162float(h1));
            const __nv_bfloat16 l2 = __float2bfloat16(v.z - __bfloat162float(h2));
            const __nv_bfloat16 l3 = __float2bfloat16(v.w - __bfloat162float(h3));
            __nv_bfloat162* dh = reinterpret_cast<__nv_bfloat162*>(sWhi + jj * PW + q);
            __nv_bfloat162* dl = reinterpret_cast<__nv_bfloat162*>(sWlo + jj * PW + q);
            dh[0] = __halves2bfloat162(h0, h1); dh[1] = __halves2bfloat162(h2, h3);
            dl[0] = __halves2bfloat162(l0, l1); dl[1] = __halves2bfloat162(l2, l3);
        }
    }

    // epilogue cell ownership (kh==0 threads): rows r0,r0+8; kc pair kc2,kc2+1
    const int r0  = wm * 16 + (lane >> 2);
    const int kc2 = wn * 8 + (lane & 3) * 2;
    float br0 = 0.f, br1 = 0.f, bz0 = 0.f, bz1 = 0.f, bn0 = 0.f, bn1 = 0.f;
    if (kh == 0) {
        br0 = b_hh[dir * GG + 0 * HH + k0 + kc2]; br1 = b_hh[dir * GG + 0 * HH + k0 + kc2 + 1];
        bz0 = b_hh[dir * GG + 1 * HH + k0 + kc2]; bz1 = b_hh[dir * GG + 1 * HH + k0 + kc2 + 1];
        bn0 = b_hh[dir * GG + 2 * HH + k0 + kc2]; bn1 = b_hh[dir * GG + 2 * HH + k0 + kc2 + 1];
    }
    float hprev[4] = {0.f, 0.f, 0.f, 0.f};
    float mx[4] = {-1e30f, -1e30f, -1e30f, -1e30f};
    unsigned bar_tgt = 0;
    __syncthreads();

    const unsigned sAb  = (unsigned)__cvta_generic_to_shared(sA);
    const unsigned sWhb = (unsigned)__cvta_generic_to_shared(sWhi);
    const unsigned sWlb = (unsigned)__cvta_generic_to_shared(sWlo);
    const int t128 = tid & 127;

    for (int s = 0; s < TT; s++) {
        const int t = dir ? (TT - 1 - s) : s;
        const int p = s & 1;

        // ---- issue own-group h chunks: hi (cols kh*256), then lo (512+kh*256)
        {
            const __nv_bfloat16* hsrc = &g_hA[p][dir][bg * 32][0];
#pragma unroll
            for (int it = 0; it < 8; it++) {
                const int idx = it * 128 + t128;
                const int row = idx >> 5, seg = idx & 31;
                const int col = kh * 256 + seg * 8;
                asm volatile("cp.async.cg.shared.global [%0], [%1], 16;"
                    :: "r"(sAb + (unsigned)((row * PA + col) << 1)),
                       "l"(hsrc + row * 1024 + col) : "memory");
            }
            asm volatile("cp.async.commit_group;" ::: "memory");
#pragma unroll
            for (int it = 0; it < 8; it++) {
                const int idx = it * 128 + t128;
                const int row = idx >> 5, seg = idx & 31;
                const int col = 512 + kh * 256 + seg * 8;
                asm volatile("cp.async.cg.shared.global [%0], [%1], 16;"
                    :: "r"(sAb + (unsigned)((row * PA + col) << 1)),
                       "l"(hsrc + row * 1024 + col) : "memory");
            }
            asm volatile("cp.async.commit_group;" ::: "memory");
        }

        // ---- prefetch xp epilogue operands (kh==0 only)
        float2 xr0, xr1, xz0, xz1, xn0, xn1;
        if (kh == 0) {
            const size_t xb0 = ((size_t)(dir * BB + bg * 32 + r0) * TT + t) * GG + k0 + kc2;
            const size_t xb1 = ((size_t)(dir * BB + bg * 32 + r0 + 8) * TT + t) * GG + k0 + kc2;
            xr0 = __ldg(reinterpret_cast<const float2*>(xp + xb0));
            xz0 = __ldg(reinterpret_cast<const float2*>(xp + xb0 + HH));
            xn0 = __ldg(reinterpret_cast<const float2*>(xp + xb0 + 2 * HH));
            xr1 = __ldg(reinterpret_cast<const float2*>(xp + xb1));
            xz1 = __ldg(reinterpret_cast<const float2*>(xp + xb1 + HH));
            xn1 = __ldg(reinterpret_cast<const float2*>(xp + xb1 + 2 * HH));
        }

        float c0[4] = {0.f, 0.f, 0.f, 0.f};
        float c1[4] = {0.f, 0.f, 0.f, 0.f};
        float c2[4] = {0.f, 0.f, 0.f, 0.f};

        // ---- phase A: hi chunk ready -> a_hi x (Whi, Wlo)
        asm volatile("cp.async.wait_group 1;" ::: "memory");
        asm volatile("bar.sync %0, 128;" :: "r"(1 + kh) : "memory");
#pragma unroll 4
        for (int kk = kh * 256; kk < kh * 256 + 256; kk += 16) {
            unsigned a0, a1, a2, a3r;
            unsigned h00, h01, h10, h11, h20, h21;
            unsigned l00, l01, l10, l11, l20, l21;
            const unsigned ad = sAb + ((((wm * 16 + (lane & 15)) * PA) + kk + (lane >> 4) * 8) << 1);
            asm volatile("ldmatrix.sync.aligned.m8n8.x4.shared.b16 {%0,%1,%2,%3}, [%4];"
                : "=r"(a0), "=r"(a1), "=r"(a2), "=r"(a3r) : "r"(ad));
            const int g_ = lane >> 3, rr_ = lane & 7;
            const unsigned bo  = (unsigned)(((wn * 24 + (g_ >> 1) * 8 + rr_) * PW + kk + (g_ & 1) * 8) << 1);
            const unsigned bo2 = (unsigned)(((wn * 24 + 16 + rr_) * PW + kk + ((lane >> 3) & 1) * 8) << 1);
            asm volatile("ldmatrix.sync.aligned.m8n8.x4.shared.b16 {%0,%1,%2,%3}, [%4];"
                : "=r"(h00), "=r"(h01), "=r"(h10), "=r"(h11) : "r"(sWhb + bo));
            asm volatile("ldmatrix.sync.aligned.m8n8.x2.shared.b16 {%0,%1}, [%2];"
                : "=r"(h20), "=r"(h21) : "r"(sWhb + bo2));
            asm volatile("ldmatrix.sync.aligned.m8n8.x4.shared.b16 {%0,%1,%2,%3}, [%4];"
                : "=r"(l00), "=r"(l01), "=r"(l10), "=r"(l11) : "r"(sWlb + bo));
            asm volatile("ldmatrix.sync.aligned.m8n8.x2.shared.b16 {%0,%1}, [%2];"
                : "=r"(l20), "=r"(l21) : "r"(sWlb + bo2));
#define MMA1(CC, B0, B1) \
            asm volatile("mma.sync.aligned.m16n8k16.row.col.f32.bf16.bf16.f32 " \
                "{%0,%1,%2,%3}, {%4,%5,%6,%7}, {%8,%9}, {%0,%1,%2,%3};" \
                : "+f"(CC[0]), "+f"(CC[1]), "+f"(CC[2]), "+f"(CC[3]) \
                : "r"(a0), "r"(a1), "r"(a2), "r"(a3r), "r"(B0), "r"(B1))
            MMA1(c0, h00, h01); MMA1(c1, h10, h11); MMA1(c2, h20, h21);
            MMA1(c0, l00, l01); MMA1(c1, l10, l11); MMA1(c2, l20, l21);
        }

        // ---- phase B: lo chunk ready -> a_lo x Whi
        asm volatile("cp.async.wait_group 0;" ::: "memory");
        asm volatile("bar.sync %0, 128;" :: "r"(1 + kh) : "memory");
#pragma unroll 4
        for (int kk = kh * 256; kk < kh * 256 + 256; kk += 16) {
            unsigned a0, a1, a2, a3r;
            unsigned h00, h01, h10, h11, h20, h21;
            const unsigned ad = sAb + ((((wm * 16 + (lane & 15)) * PA) + 512 + kk + (lane >> 4) * 8) << 1);
            asm volatile("ldmatrix.sync.aligned.m8n8.x4.shared.b16 {%0,%1,%2,%3}, [%4];"
                : "=r"(a0), "=r"(a1), "=r"(a2), "=r"(a3r) : "r"(ad));
            const int g_ = lane >> 3, rr_ = lane & 7;
            const unsigned bo  = (unsigned)(((wn * 24 + (g_ >> 1) * 8 + rr_) * PW + kk + (g_ & 1) * 8) << 1);
            const unsigned bo2 = (unsigned)(((wn * 24 + 16 + rr_) * PW + kk + ((lane >> 3) & 1) * 8) << 1);
            asm volatile("ldmatrix.sync.aligned.m8n8.x4.shared.b16 {%0,%1,%2,%3}, [%4];"
                : "=r"(h00), "=r"(h01), "=r"(h10), "=r"(h11) : "r"(sWhb + bo));
            asm volatile("ldmatrix.sync.aligned.m8n8.x2.shared.b16 {%0,%1}, [%2];"
                : "=r"(h20), "=r"(h21) : "r"(sWhb + bo2));
            MMA1(c0, h00, h01); MMA1(c1, h10, h11); MMA1(c2, h20, h21);
        }

        // ---- reduce k-halves
        if (kh == 1) {
            float* rp = sred + (size_t)(((warp - 4) << 5) + lane) * 13;
#pragma unroll
            for (int q = 0; q < 4; q++) {
                rp[q] = c0[q]; rp[4 + q] = c1[q]; rp[8 + q] = c2[q];
            }
        }
        __syncthreads();
        if (kh == 0) {
            const float* rp = sred + (size_t)((warp << 5) + lane) * 13;
            float hv[4];
#pragma unroll
            for (int q = 0; q < 4; q++) {
                const float gr = c0[q] + rp[q]     + ((q & 1) ? br1 : br0);
                const float gz = c1[q] + rp[4 + q] + ((q & 1) ? bz1 : bz0);
                const float gn = c2[q] + rp[8 + q] + ((q & 1) ? bn1 : bn0);
                const float2 xr = (q >> 1) ? xr1 : xr0;
                const float2 xz = (q >> 1) ? xz1 : xz0;
                const float2 xn = (q >> 1) ? xn1 : xn0;
                const float rg = fast_sig(((q & 1) ? xr.y : xr.x) + gr);
                const float zg = fast_sig(((q & 1) ? xz.y : xz.x) + gz);
                const float ng = fast_tanh(((q & 1) ? xn.y : xn.x) + rg * gn);
                hv[q] = (1.f - zg) * ng + zg * hprev[q];
                hprev[q] = hv[q];
                if (do_pool) mx[q] = fmaxf(mx[q], hv[q]);
            }
            // split h, store both rows
#pragma unroll
            for (int rsel = 0; rsel < 2; rsel++) {
                const float v0 = hv[rsel * 2], v1 = hv[rsel * 2 + 1];
                const __nv_bfloat16 h0 = __float2bfloat16(v0);
                const __nv_bfloat16 h1 = __float2bfloat16(v1);
                const __nv_bfloat16 l0 = __float2bfloat16(v0 - __bfloat162float(h0));
                const __nv_bfloat16 l1 = __float2bfloat16(v1 - __bfloat162float(h1));
                const __nv_bfloat162 hp2 = __halves2bfloat162(h0, h1);
                const __nv_bfloat162 lp2 = __halves2bfloat162(l0, l1);
                const int brow = bg * 32 + r0 + rsel * 8;
                __nv_bfloat16* dst = &g_hA[1 - p][dir][brow][k0 + kc2];
                __stcg(reinterpret_cast<unsigned*>(dst),
                       *reinterpret_cast<const unsigned*>(&hp2));
                __stcg(reinterpret_cast<unsigned*>(dst + 512),
                       *reinterpret_cast<const unsigned*>(&lp2));
                if (a3) {
                    // layer-1 A split [hi | hi | lo], Kp=1024
                    __nv_bfloat16* ad3 = a3 + ((size_t)brow * TT + t) * 3072 + dir * HH + k0 + kc2;
                    *reinterpret_cast<unsigned*>(ad3)        = *reinterpret_cast<const unsigned*>(&hp2);
                    *reinterpret_cast<unsigned*>(ad3 + 1024) = *reinterpret_cast<const unsigned*>(&hp2);
                    *reinterpret_cast<unsigned*>(ad3 + 2048) = *reinterpret_cast<const unsigned*>(&lp2);
                }
            }
        }
        group_barrier(bar, bar_tgt, 32u);
    }

    if (do_pool && kh == 0) {
#pragma unroll
        for (int q = 0; q < 4; q++) {
            const int brow = bg * 32 + r0 + (q >> 1) * 8;
            g_pooled[(size_t)brow * (2 * HH) + dir * HH + k0 + kc2 + (q & 1)] = mx[q];
        }
    }
}

// ---------------- classifier head ----------------
__global__ void mlp1_kernel(const float* __restrict__ w1, const float* __restrict__ b1) {
    const int warp = (blockIdx.x * blockDim.x + threadIdx.x) >> 5;
    const int lane = threadIdx.x & 31;
    if (warp >= BB * 128) return;
    const int b = warp >> 7, j = warp & 127;
    const float* p = g_pooled + (size_t)b * 2 * HH;
    const float* w = w1 + (size_t)j * 2 * HH;
    float s = 0.f;
    for (int k = lane; k < 2 * HH; k += 32) s = fmaf(p[k], w[k], s);
#pragma unroll
    for (int o = 16; o; o >>= 1) s += __shfl_xor_sync(0xffffffffu, s, o);
    if (lane == 0) g_hid[b * 128 + j] = fmaxf(s + b1[j], 0.f);
}

__global__ void mlp2_kernel(const float* __restrict__ w2, const float* __restrict__ b2,
                            float* __restrict__ out) {
    const int t = threadIdx.x;
    if (t < BB * 2) {
        const int b = t >> 1, c = t & 1;
        float s = b2[c];
        const float* h = g_hid + b * 128;
        const float* w = w2 + c * 128;
        for (int k = 0; k < 128; k++) s = fmaf(h[k], w[k], s);
        out[t] = s;
    }
}

// ---------------- launch ----------------
extern "C" void kernel_launch(void* const* d_in, const int* in_sizes, int n_in,
                              void* d_out, int out_size) {
    const int*   x    = (const int*)d_in[0];
    const float* emb  = (const float*)d_in[1];
    const float* wih0 = (const float*)d_in[2];
    const float* whh0 = (const float*)d_in[3];
    const float* bih0 = (const float*)d_in[4];
    const float* bhh0 = (const float*)d_in[5];
    const float* wih1 = (const float*)d_in[6];
    const float* whh1 = (const float*)d_in[7];
    const float* bih1 = (const float*)d_in[8];
    const float* bhh1 = (const float*)d_in[9];
    const float* w1   = (const float*)d_in[10];
    const float* b1   = (const float*)d_in[11];
    const float* w2   = (const float*)d_in[12];
    const float* b2   = (const float*)d_in[13];

    float *e_p = nullptr, *xp_p = nullptr;
    __nv_bfloat16 *a3_p = nullptr, *w3_p = nullptr;
    cudaGetSymbolAddress((void**)&e_p,  g_e);
    cudaGetSymbolAddress((void**)&xp_p, g_xp);
    cudaGetSymbolAddress((void**)&a3_p, g_a3);
    cudaGetSymbolAddress((void**)&w3_p, g_w3);

    const size_t sm_tc = (size_t)(2 * 48 * PW + 32 * PA) * sizeof(__nv_bfloat16)
                       + (size_t)(128 * 13) * sizeof(float);
    cudaFuncSetAttribute(recur_tc_kernel, cudaFuncAttributeMaxDynamicSharedMemorySize, (int)sm_tc);

    // ---- layer 0 ----
    init_kernel<<<64, 256>>>();
    embed_kernel<<<MM, 128>>>(x, emb);
    {
        const long pa = (long)MM * (320 / 2);
        conv_split_kernel<<<(unsigned)((pa + 255) / 256), 256>>>(e_p, a3_p, MM, EE, 320, 0);
        const long pw = (long)(2 * GG) * (320 / 2);
        conv_split_kernel<<<(unsigned)((pw + 255) / 256), 256>>>(wih0, w3_p, 2 * GG, EE, 320, 1);
    }
    bgemm_kernel<<<dim3(GG / 128, MM / 128, 2), 256>>>(a3_p, w3_p, bih0, xp_p, MM, GG, 960);
    // W split for layer 1 (independent; overlaps recurrence tail in-stream order anyway)
    {
        const long pw = (long)(2 * GG) * (1024 / 2);
        conv_split_kernel<<<(unsigned)((pw + 255) / 256), 256>>>(wih1, w3_p, 2 * GG, 2 * HH, 1024, 1);
    }
    recur_tc_kernel<<<128, 256, sm_tc>>>(xp_p, whh0, bhh0, a3_p, 0);  // writes layer-1 split A

    // ---- layer 1 ----
    bgemm_kernel<<<dim3(GG / 128, MM / 128, 2), 256>>>(a3_p, w3_p, bih1, xp_p, MM, GG, 3072);
    init_kernel<<<64, 256>>>();
    recur_tc_kernel<<<128, 256, sm_tc>>>(xp_p, whh1, bhh1, nullptr, 1);

    // ---- head ----
    mlp1_kernel<<<(BB * 128 * 32) / 256, 256>>>(w1, b1);
    mlp2_kernel<<<1, 128>>>(w2, b2, (float*)d_out);
}

// round 7
// speedup vs baseline: 2.9512x; 1.0355x over previous
#include <cuda_runtime.h>
#include <cuda_bf16.h>
#include <math.h>

#define BB 64
#define TT 256
#define EE 300
#define HH 512
#define GG 1536               // 3*H
#define MM (BB*TT)            // 16384

// ---------------- scratch (static device allocations only) ----------------
__device__ __align__(256) float g_xp[2 * MM * GG];       // input projections [dir][B*T, 1536]
__device__ __align__(256) __nv_bfloat16 g_hA[2][2][BB][1024]; // h split [buf][dir][b][hi|lo]
__device__ __align__(256) float g_pooled[BB * 2 * HH];   // maxpool [B, 1024]
__device__ __align__(256) float g_hid[BB * 128];         // mlp hidden
__device__ __align__(256) __nv_bfloat16 g_a3[MM * 3 * 1024];        // split A [M, 3*Kp]
__device__ __align__(256) __nv_bfloat16 g_w3[2 * GG * 3 * 1024];    // split W [2N, 3*Kp]
__device__ unsigned g_bar4[4];

// ---------------- init ----------------
__global__ void init_kernel() {
    const int n = 2 * 2 * BB * 1024 / 2;
    unsigned* p = reinterpret_cast<unsigned*>(&g_hA[0][0][0][0]);
    for (int i = blockIdx.x * blockDim.x + threadIdx.x; i < n; i += gridDim.x * blockDim.x)
        p[i] = 0u;
    if (blockIdx.x == 0 && threadIdx.x < 4) g_bar4[threadIdx.x] = 0u;
}

// ---------------- fused embedding gather + bf16 split (A slabs [hi|hi|lo], Kp=320) ----------------
__global__ void embed_split_kernel(const int* __restrict__ x, const float* __restrict__ emb) {
    const int tok = blockIdx.x;
    const int row = x[tok];
    const int pi = threadIdx.x;          // pair index 0..159
    const int k0 = pi * 2;
    const float v0 = (k0     < EE) ? emb[(size_t)row * EE + k0]     : 0.f;
    const float v1 = (k0 + 1 < EE) ? emb[(size_t)row * EE + k0 + 1] : 0.f;
    const __nv_bfloat16 h0 = __float2bfloat16(v0), h1 = __float2bfloat16(v1);
    const __nv_bfloat16 l0 = __float2bfloat16(v0 - __bfloat162float(h0));
    const __nv_bfloat16 l1 = __float2bfloat16(v1 - __bfloat162float(h1));
    const __nv_bfloat162 hh = __halves2bfloat162(h0, h1);
    const __nv_bfloat162 ll = __halves2bfloat162(l0, l1);
    __nv_bfloat162* d = reinterpret_cast<__nv_bfloat162*>(g_a3 + (size_t)tok * 960);
    d[pi] = hh; d[pi + 160] = hh; d[pi + 320] = ll;
}

// ---------------- bf16 split conversion (weights) ----------------
__global__ void conv_split_kernel(const float* __restrict__ src, __nv_bfloat16* __restrict__ dst,
                                  int rows, int Ksrc, int Kp, int mode) {
    const long i = (long)blockIdx.x * blockDim.x + threadIdx.x;
    const long total = (long)rows * (Kp / 2);
    if (i >= total) return;
    const int m  = (int)(i / (Kp / 2));
    const int k0 = (int)(i % (Kp / 2)) * 2;
    const float v0 = (k0     < Ksrc) ? src[(size_t)m * Ksrc + k0]     : 0.f;
    const float v1 = (k0 + 1 < Ksrc) ? src[(size_t)m * Ksrc + k0 + 1] : 0.f;
    const __nv_bfloat16 h0 = __float2bfloat16(v0), h1 = __float2bfloat16(v1);
    const __nv_bfloat16 l0 = __float2bfloat16(v0 - __bfloat162float(h0));
    const __nv_bfloat16 l1 = __float2bfloat16(v1 - __bfloat162float(h1));
    const __nv_bfloat162 hh = __halves2bfloat162(h0, h1);
    const __nv_bfloat162 ll = __halves2bfloat162(l0, l1);
    __nv_bfloat162* d = reinterpret_cast<__nv_bfloat162*>(dst + (size_t)m * 3 * Kp);
    const int p = k0 >> 1, s = Kp >> 1;
    if (mode == 0) { d[p] = hh; d[p + s] = hh; d[p + 2 * s] = ll; }
    else           { d[p] = hh; d[p + s] = ll; d[p + 2 * s] = hh; }
}

// ---------------- bf16 tensor-core GEMM, 3-stage cp.async pipeline ----------------
#define PKH 40
__global__ void __launch_bounds__(256, 2) bgemm_kernel(
    const __nv_bfloat16* __restrict__ A, const __nv_bfloat16* __restrict__ W,
    const float* __restrict__ bias, float* __restrict__ C, int M, int N, int K3)
{
    extern __shared__ __nv_bfloat16 gsm[];
    __nv_bfloat16* As = gsm;                    // [3][128*PKH]
    __nv_bfloat16* Bs = gsm + 3 * 128 * PKH;    // [3][128*PKH]

    const int z = blockIdx.z;
    W    += (size_t)z * N * K3;
    bias += (size_t)z * N;
    C    += (size_t)z * M * N;

    const int m0 = blockIdx.y * 128, n0 = blockIdx.x * 128;
    const int tid = threadIdx.x;
    const int warp = tid >> 5, lane = tid & 31;
    const int wm = warp >> 2, wn = warp & 3;

    float c[4][4][4];
#pragma unroll
    for (int mi = 0; mi < 4; mi++)
#pragma unroll
        for (int ni = 0; ni < 4; ni++)
#pragma unroll
            for (int q = 0; q < 4; q++) c[mi][ni][q] = 0.f;

    const int lrow = tid >> 2;
    const int lcol = (tid & 3) * 8;
    const unsigned asb = (unsigned)__cvta_generic_to_shared(As);
    const unsigned bsb = (unsigned)__cvta_generic_to_shared(Bs);
    const int nk = K3 / 32;

#define BG_ISSUE(KT, BUF) do {                                                        \
        const int kg_ = (KT) * 32 + lcol;                                             \
        const size_t ar_ = (size_t)(m0 + lrow) * K3 + kg_;                            \
        const size_t br_ = (size_t)(n0 + lrow) * K3 + kg_;                            \
        const unsigned ao_ = (unsigned)((((BUF) * 128 + lrow) * PKH + lcol) << 1);    \
        asm volatile("cp.async.cg.shared.global [%0],[%1],16;"                        \
            :: "r"(asb + ao_), "l"(A + ar_) : "memory");                              \
        asm volatile("cp.async.cg.shared.global [%0],[%1],16;"                        \
            :: "r"(asb + ao_ + (unsigned)((64 * PKH) << 1)), "l"(A + ar_ + (size_t)64 * K3) : "memory"); \
        asm volatile("cp.async.cg.shared.global [%0],[%1],16;"                        \
            :: "r"(bsb + ao_), "l"(W + br_) : "memory");                              \
        asm volatile("cp.async.cg.shared.global [%0],[%1],16;"                        \
            :: "r"(bsb + ao_ + (unsigned)((64 * PKH) << 1)), "l"(W + br_ + (size_t)64 * K3) : "memory"); \
        asm volatile("cp.async.commit_group;" ::: "memory");                          \
    } while (0)

    BG_ISSUE(0, 0);
    if (nk > 1) BG_ISSUE(1, 1);

    for (int kt = 0; kt < nk; kt++) {
        if (kt + 1 < nk) asm volatile("cp.async.wait_group 1;" ::: "memory");
        else             asm volatile("cp.async.wait_group 0;" ::: "memory");
        __syncthreads();
        if (kt + 2 < nk) BG_ISSUE(kt + 2, (kt + 2) % 3);

        const unsigned abase = asb + (unsigned)(((kt % 3) * 128 * PKH) << 1);
        const unsigned bbase = bsb + (unsigned)(((kt % 3) * 128 * PKH) << 1);

#pragma unroll
        for (int kk = 0; kk < 32; kk += 16) {
            unsigned a[4][4], b[4][2];
#pragma unroll
            for (int mi = 0; mi < 4; mi++) {
                const unsigned ad = abase +
                    (((wm * 64 + mi * 16 + (lane & 15)) * PKH + kk + (lane >> 4) * 8) << 1);
                asm volatile("ldmatrix.sync.aligned.m8n8.x4.shared.b16 {%0,%1,%2,%3}, [%4];"
                    : "=r"(a[mi][0]), "=r"(a[mi][1]), "=r"(a[mi][2]), "=r"(a[mi][3]) : "r"(ad));
            }
#pragma unroll
            for (int nj = 0; nj < 2; nj++) {
                const int g = lane >> 3, rr = lane & 7;
                const unsigned bd = bbase +
                    (((wn * 32 + nj * 16 + (g >> 1) * 8 + rr) * PKH + kk + (g & 1) * 8) << 1);
                asm volatile("ldmatrix.sync.aligned.m8n8.x4.shared.b16 {%0,%1,%2,%3}, [%4];"
                    : "=r"(b[nj * 2][0]), "=r"(b[nj * 2][1]),
                      "=r"(b[nj * 2 + 1][0]), "=r"(b[nj * 2 + 1][1]) : "r"(bd));
            }
#pragma unroll
            for (int mi = 0; mi < 4; mi++)
#pragma unroll
                for (int ni = 0; ni < 4; ni++)
                    asm volatile(
                        "mma.sync.aligned.m16n8k16.row.col.f32.bf16.bf16.f32 "
                        "{%0,%1,%2,%3}, {%4,%5,%6,%7}, {%8,%9}, {%0,%1,%2,%3};"
                        : "+f"(c[mi][ni][0]), "+f"(c[mi][ni][1]),
                          "+f"(c[mi][ni][2]), "+f"(c[mi][ni][3])
                        : "r"(a[mi][0]), "r"(a[mi][1]), "r"(a[mi][2]), "r"(a[mi][3]),
                          "r"(b[ni][0]), "r"(b[ni][1]));
        }
    }

#pragma unroll
    for (int mi = 0; mi < 4; mi++) {
        const int row = m0 + wm * 64 + mi * 16 + (lane >> 2);
#pragma unroll
        for (int ni = 0; ni < 4; ni++) {
            const int col = n0 + wn * 32 + ni * 8 + (lane & 3) * 2;
            const float bx = bias[col], by = bias[col + 1];
            float2 v0 = make_float2(c[mi][ni][0] + bx, c[mi][ni][1] + by);
            float2 v1 = make_float2(c[mi][ni][2] + bx, c[mi][ni][3] + by);
            *reinterpret_cast<float2*>(&C[(size_t)row * N + col]) = v0;
            *reinterpret_cast<float2*>(&C[(size_t)(row + 8) * N + col]) = v1;
        }
    }
}

__device__ __forceinline__ float fast_sig(float x) {
    return __fdividef(1.f, 1.f + __expf(-x));
}
__device__ __forceinline__ float fast_tanh(float x) {
    return 1.f - __fdividef(2.f, __expf(2.f * x) + 1.f);
}

// ---------------- tensor-core persistent BiGRU recurrence ----------------
// 128 CTAs: dir = cta>>6, ks = (cta&63)>>1 (16 k-cols), bg = cta&1 (32 batches).
// Arrive/wait split: arrive after h stores; wait just before next h load;
// a3/pool stores + xp prefetch live inside the spin window.
#define PA 1032   // A smem pitch (halves)
#define PW 520    // W smem pitch (halves)
__global__ void __launch_bounds__(256, 1) recur_tc_kernel(
    const float* __restrict__ xp,    // [dir][B*T, 1536] (includes b_ih)
    const float* __restrict__ w_hh,  // [2][1536][512]
    const float* __restrict__ b_hh,  // [2][1536]
    __nv_bfloat16* __restrict__ a3,  // layer-1 split A out [M, 3*1024] or nullptr
    int do_pool)
{
    extern __shared__ char smraw[];
    __nv_bfloat16* sWhi = reinterpret_cast<__nv_bfloat16*>(smraw);   // [48][PW]
    __nv_bfloat16* sWlo = sWhi + 48 * PW;                             // [48][PW]
    __nv_bfloat16* sA   = sWlo + 48 * PW;                             // [32][PA]
    float* sred  = reinterpret_cast<float*>(sA + 32 * PA);            // [128][13]

    const int cta = blockIdx.x;
    const int dir = cta >> 6;
    const int ks  = (cta & 63) >> 1;
    const int bg  = cta & 1;
    const int k0  = ks * 16;
    const int tid = threadIdx.x;
    const int warp = tid >> 5, lane = tid & 31;
    const int kh = warp >> 2;
    const int wm = (warp >> 1) & 1;
    const int wn = warp & 1;
    unsigned* bar = &g_bar4[dir * 2 + bg];

    // ---- load + split W_hh slice, rows ordered [blk(2)][gate(3)][kcl(8)]
    {
        const float* wsrc = w_hh + (size_t)dir * GG * HH;
        for (int idx = tid; idx < 48 * 128; idx += 256) {
            const int jj = idx >> 7;
            const int q  = (idx & 127) * 4;
            const int blk = jj / 24, within = jj % 24;
            const int gate = within >> 3, kcl = within & 7;
            const int grow = gate * HH + k0 + blk * 8 + kcl;
            const float4 v = *reinterpret_cast<const float4*>(&wsrc[(size_t)grow * HH + q]);
            const __nv_bfloat16 h0 = __float2bfloat16(v.x), h1 = __float2bfloat16(v.y);
            const __nv_bfloat16 h2 = __float2bfloat16(v.z), h3 = __float2bfloat16(v.w);
            const __nv_bfloat16 l0 = __float2bfloat16(v.x - __bfloat162float(h0));
            const __nv_bfloat16 l1 = __float2bfloat16(v.y - __bfloat162float(h1));
            const __nv_bfloat16 l2 = __float2bfloat16(v.z - __bfloat162float(h2));
            const __nv_bfloat16 l3 = __float2bfloat16(v.w - __bfloat162float(h3));
            __nv_bfloat162* dh = reinterpret_cast<__nv_bfloat162*>(sWhi + jj * PW + q);
            __nv_bfloat162* dl = reinterpret_cast<__nv_bfloat162*>(sWlo + jj * PW + q);
            dh[0] = __halves2bfloat162(h0, h1); dh[1] = __halves2bfloat162(h2, h3);
            dl[0] = __halves2bfloat162(l0, l1); dl[1] = __halves2bfloat162(l2, l3);
        }
    }

    const int r0  = wm * 16 + (lane >> 2);
    const int kc2 = wn * 8 + (lane & 3) * 2;
    float br0 = 0.f, br1 = 0.f, bz0 = 0.f, bz1 = 0.f, bn0 = 0.f, bn1 = 0.f;
    if (kh == 0) {
        br0 = b_hh[dir * GG + 0 * HH + k0 + kc2]; br1 = b_hh[dir * GG + 0 * HH + k0 + kc2 + 1];
        bz0 = b_hh[dir * GG + 1 * HH + k0 + kc2]; bz1 = b_hh[dir * GG + 1 * HH + k0 + kc2 + 1];
        bn0 = b_hh[dir * GG + 2 * HH + k0 + kc2]; bn1 = b_hh[dir * GG + 2 * HH + k0 + kc2 + 1];
    }
    float hprev[4] = {0.f, 0.f, 0.f, 0.f};
    float mx[4] = {-1e30f, -1e30f, -1e30f, -1e30f};
    unsigned bar_tgt = 0;
    __syncthreads();

    const unsigned sAb  = (unsigned)__cvta_generic_to_shared(sA);
    const unsigned sWhb = (unsigned)__cvta_generic_to_shared(sWhi);
    const unsigned sWlb = (unsigned)__cvta_generic_to_shared(sWlo);
    const int t128 = tid & 127;

    for (int s = 0; s < TT; s++) {
        const int t = dir ? (TT - 1 - s) : s;
        const int p = s & 1;

        // ---- spin-window work: prefetch xp epilogue operands (kh==0 only)
        float2 xr0, xr1, xz0, xz1, xn0, xn1;
        if (kh == 0) {
            const size_t xb0 = ((size_t)(dir * BB + bg * 32 + r0) * TT + t) * GG + k0 + kc2;
            const size_t xb1 = ((size_t)(dir * BB + bg * 32 + r0 + 8) * TT + t) * GG + k0 + kc2;
            xr0 = __ldg(reinterpret_cast<const float2*>(xp + xb0));
            xz0 = __ldg(reinterpret_cast<const float2*>(xp + xb0 + HH));
            xn0 = __ldg(reinterpret_cast<const float2*>(xp + xb0 + 2 * HH));
            xr1 = __ldg(reinterpret_cast<const float2*>(xp + xb1));
            xz1 = __ldg(reinterpret_cast<const float2*>(xp + xb1 + HH));
            xn1 = __ldg(reinterpret_cast<const float2*>(xp + xb1 + 2 * HH));
        }

        // ---- wait for step-s h (counter >= 32*s)
        if (tid == 0 && s > 0) {
            unsigned v;
            do {
                asm volatile("ld.acquire.gpu.global.u32 %0, [%1];"
                             : "=r"(v) : "l"(bar) : "memory");
            } while (v < bar_tgt);
        }
        __syncthreads();

        // ---- issue own-group h chunks: hi (cols kh*256), then lo (512+kh*256)
        {
            const __nv_bfloat16* hsrc = &g_hA[p][dir][bg * 32][0];
#pragma unroll
            for (int it = 0; it < 8; it++) {
                const int idx = it * 128 + t128;
                const int row = idx >> 5, seg = idx & 31;
                const int col = kh * 256 + seg * 8;
                asm volatile("cp.async.cg.shared.global [%0], [%1], 16;"
                    :: "r"(sAb + (unsigned)((row * PA + col) << 1)),
                       "l"(hsrc + row * 1024 + col) : "memory");
            }
            asm volatile("cp.async.commit_group;" ::: "memory");
#pragma unroll
            for (int it = 0; it < 8; it++) {
                const int idx = it * 128 + t128;
                const int row = idx >> 5, seg = idx & 31;
                const int col = 512 + kh * 256 + seg * 8;
                asm volatile("cp.async.cg.shared.global [%0], [%1], 16;"
                    :: "r"(sAb + (unsigned)((row * PA + col) << 1)),
                       "l"(hsrc + row * 1024 + col) : "memory");
            }
            asm volatile("cp.async.commit_group;" ::: "memory");
        }

        float c0[4] = {0.f, 0.f, 0.f, 0.f};
        float c1[4] = {0.f, 0.f, 0.f, 0.f};
        float c2[4] = {0.f, 0.f, 0.f, 0.f};

        // ---- phase A: hi chunk ready -> a_hi x (Whi, Wlo)
        asm volatile("cp.async.wait_group 1;" ::: "memory");
        asm volatile("bar.sync %0, 128;" :: "r"(1 + kh) : "memory");
#pragma unroll 4
        for (int kk = kh * 256; kk < kh * 256 + 256; kk += 16) {
            unsigned a0, a1, a2, a3r;
            unsigned h00, h01, h10, h11, h20, h21;
            unsigned l00, l01, l10, l11, l20, l21;
            const unsigned ad = sAb + ((((wm * 16 + (lane & 15)) * PA) + kk + (lane >> 4) * 8) << 1);
            asm volatile("ldmatrix.sync.aligned.m8n8.x4.shared.b16 {%0,%1,%2,%3}, [%4];"
                : "=r"(a0), "=r"(a1), "=r"(a2), "=r"(a3r) : "r"(ad));
            const int g_ = lane >> 3, rr_ = lane & 7;
            const unsigned bo  = (unsigned)(((wn * 24 + (g_ >> 1) * 8 + rr_) * PW + kk + (g_ & 1) * 8) << 1);
            const unsigned bo2 = (unsigned)(((wn * 24 + 16 + rr_) * PW + kk + ((lane >> 3) & 1) * 8) << 1);
            asm volatile("ldmatrix.sync.aligned.m8n8.x4.shared.b16 {%0,%1,%2,%3}, [%4];"
                : "=r"(h00), "=r"(h01), "=r"(h10), "=r"(h11) : "r"(sWhb + bo));
            asm volatile("ldmatrix.sync.aligned.m8n8.x2.shared.b16 {%0,%1}, [%2];"
                : "=r"(h20), "=r"(h21) : "r"(sWhb + bo2));
            asm volatile("ldmatrix.sync.aligned.m8n8.x4.shared.b16 {%0,%1,%2,%3}, [%4];"
                : "=r"(l00), "=r"(l01), "=r"(l10), "=r"(l11) : "r"(sWlb + bo));
            asm volatile("ldmatrix.sync.aligned.m8n8.x2.shared.b16 {%0,%1}, [%2];"
                : "=r"(l20), "=r"(l21) : "r"(sWlb + bo2));
#define MMA1(CC, B0, B1) \
            asm volatile("mma.sync.aligned.m16n8k16.row.col.f32.bf16.bf16.f32 " \
                "{%0,%1,%2,%3}, {%4,%5,%6,%7}, {%8,%9}, {%0,%1,%2,%3};" \
                : "+f"(CC[0]), "+f"(CC[1]), "+f"(CC[2]), "+f"(CC[3]) \
                : "r"(a0), "r"(a1), "r"(a2), "r"(a3r), "r"(B0), "r"(B1))
            MMA1(c0, h00, h01); MMA1(c1, h10, h11); MMA1(c2, h20, h21);
            MMA1(c0, l00, l01); MMA1(c1, l10, l11); MMA1(c2, l20, l21);
        }

        // ---- phase B: lo chunk ready -> a_lo x Whi
        asm volatile("cp.async.wait_group 0;" ::: "memory");
        asm volatile("bar.sync %0, 128;" :: "r"(1 + kh) : "memory");
#pragma unroll 4
        for (int kk = kh * 256; kk < kh * 256 + 256; kk += 16) {
            unsigned a0, a1, a2, a3r;
            unsigned h00, h01, h10, h11, h20, h21;
            const unsigned ad = sAb + ((((wm * 16 + (lane & 15)) * PA) + 512 + kk + (lane >> 4) * 8) << 1);
            asm volatile("ldmatrix.sync.aligned.m8n8.x4.shared.b16 {%0,%1,%2,%3}, [%4];"
                : "=r"(a0), "=r"(a1), "=r"(a2), "=r"(a3r) : "r"(ad));
            const int g_ = lane >> 3, rr_ = lane & 7;
            const unsigned bo  = (unsigned)(((wn * 24 + (g_ >> 1) * 8 + rr_) * PW + kk + (g_ & 1) * 8) << 1);
            const unsigned bo2 = (unsigned)(((wn * 24 + 16 + rr_) * PW + kk + ((lane >> 3) & 1) * 8) << 1);
            asm volatile("ldmatrix.sync.aligned.m8n8.x4.shared.b16 {%0,%1,%2,%3}, [%4];"
                : "=r"(h00), "=r"(h01), "=r"(h10), "=r"(h11) : "r"(sWhb + bo));
            asm volatile("ldmatrix.sync.aligned.m8n8.x2.shared.b16 {%0,%1}, [%2];"
                : "=r"(h20), "=r"(h21) : "r"(sWhb + bo2));
            MMA1(c0, h00, h01); MMA1(c1, h10, h11); MMA1(c2, h20, h21);
        }

        // ---- reduce k-halves
        if (kh == 1) {
            float* rp = sred + (size_t)(((warp - 4) << 5) + lane) * 13;
#pragma unroll
            for (int q = 0; q < 4; q++) {
                rp[q] = c0[q]; rp[4 + q] = c1[q]; rp[8 + q] = c2[q];
            }
        }
        __syncthreads();

        float hv[4];
        __nv_bfloat162 hp2[2], lp2[2];
        if (kh == 0) {
            const float* rp = sred + (size_t)((warp << 5) + lane) * 13;
#pragma unroll
            for (int q = 0; q < 4; q++) {
                const float gr = c0[q] + rp[q]     + ((q & 1) ? br1 : br0);
                const float gz = c1[q] + rp[4 + q] + ((q & 1) ? bz1 : bz0);
                const float gn = c2[q] + rp[8 + q] + ((q & 1) ? bn1 : bn0);
                const float2 xr = (q >> 1) ? xr1 : xr0;
                const float2 xz = (q >> 1) ? xz1 : xz0;
                const float2 xn = (q >> 1) ? xn1 : xn0;
                const float rg = fast_sig(((q & 1) ? xr.y : xr.x) + gr);
                const float zg = fast_sig(((q & 1) ? xz.y : xz.x) + gz);
                const float ng = fast_tanh(((q & 1) ? xn.y : xn.x) + rg * gn);
                hv[q] = (1.f - zg) * ng + zg * hprev[q];
                hprev[q] = hv[q];
            }
            // split h, store both rows to next buffer (these must precede arrive)
#pragma unroll
            for (int rsel = 0; rsel < 2; rsel++) {
                const float v0 = hv[rsel * 2], v1 = hv[rsel * 2 + 1];
                const __nv_bfloat16 h0 = __float2bfloat16(v0);
                const __nv_bfloat16 h1 = __float2bfloat16(v1);
                const __nv_bfloat16 l0 = __float2bfloat16(v0 - __bfloat162float(h0));
                const __nv_bfloat16 l1 = __float2bfloat16(v1 - __bfloat162float(h1));
                hp2[rsel] = __halves2bfloat162(h0, h1);
                lp2[rsel] = __halves2bfloat162(l0, l1);
                const int brow = bg * 32 + r0 + rsel * 8;
                __nv_bfloat16* dst = &g_hA[1 - p][dir][brow][k0 + kc2];
                __stcg(reinterpret_cast<unsigned*>(dst),
                       *reinterpret_cast<const unsigned*>(&hp2[rsel]));
                __stcg(reinterpret_cast<unsigned*>(dst + 512),
                       *reinterpret_cast<const unsigned*>(&lp2[rsel]));
            }
        }
        __syncthreads();
        // ---- arrive (release h stores), then do deferred output work in spin window
        if (tid == 0) {
            bar_tgt += 32u;
            unsigned prev;
            asm volatile("atom.acq_rel.gpu.global.add.u32 %0, [%1], 1;"
                         : "=r"(prev) : "l"(bar) : "memory");
            (void)prev;
        } else {
            bar_tgt += 32u;
        }
        if (kh == 0) {
            if (do_pool) {
#pragma unroll
                for (int q = 0; q < 4; q++) mx[q] = fmaxf(mx[q], hv[q]);
            }
            if (a3) {
#pragma unroll
                for (int rsel = 0; rsel < 2; rsel++) {
                    const int brow = bg * 32 + r0 + rsel * 8;
                    __nv_bfloat16* ad3 = a3 + ((size_t)brow * TT + t) * 3072 + dir * HH + k0 + kc2;
                    *reinterpret_cast<unsigned*>(ad3)        = *reinterpret_cast<const unsigned*>(&hp2[rsel]);
                    *reinterpret_cast<unsigned*>(ad3 + 1024) = *reinterpret_cast<const unsigned*>(&hp2[rsel]);
                    *reinterpret_cast<unsigned*>(ad3 + 2048) = *reinterpret_cast<const unsigned*>(&lp2[rsel]);
                }
            }
        }
    }

    if (do_pool && kh == 0) {
#pragma unroll
        for (int q = 0; q < 4; q++) {
            const int brow = bg * 32 + r0 + (q >> 1) * 8;
            g_pooled[(size_t)brow * (2 * HH) + dir * HH + k0 + kc2 + (q & 1)] = mx[q];
        }
    }
}

// ---------------- classifier head ----------------
__global__ void mlp1_kernel(const float* __restrict__ w1, const float* __restrict__ b1) {
    const int warp = (blockIdx.x * blockDim.x + threadIdx.x) >> 5;
    const int lane = threadIdx.x & 31;
    if (warp >= BB * 128) return;
    const int b = warp >> 7, j = warp & 127;
    const float* p = g_pooled + (size_t)b * 2 * HH;
    const float* w = w1 + (size_t)j * 2 * HH;
    float s = 0.f;
    for (int k = lane; k < 2 * HH; k += 32) s = fmaf(p[k], w[k], s);
#pragma unroll
    for (int o = 16; o; o >>= 1) s += __shfl_xor_sync(0xffffffffu, s, o);
    if (lane == 0) g_hid[b * 128 + j] = fmaxf(s + b1[j], 0.f);
}

__global__ void mlp2_kernel(const float* __restrict__ w2, const float* __restrict__ b2,
                            float* __restrict__ out) {
    const int t = threadIdx.x;
    if (t < BB * 2) {
        const int b = t >> 1, c = t & 1;
        float s = b2[c];
        const float* h = g_hid + b * 128;
        const float* w = w2 + c * 128;
        for (int k = 0; k < 128; k++) s = fmaf(h[k], w[k], s);
        out[t] = s;
    }
}

// ---------------- launch ----------------
extern "C" void kernel_launch(void* const* d_in, const int* in_sizes, int n_in,
                              void* d_out, int out_size) {
    const int*   x    = (const int*)d_in[0];
    const float* emb  = (const float*)d_in[1];
    const float* wih0 = (const float*)d_in[2];
    const float* whh0 = (const float*)d_in[3];
    const float* bih0 = (const float*)d_in[4];
    const float* bhh0 = (const float*)d_in[5];
    const float* wih1 = (const float*)d_in[6];
    const float* whh1 = (const float*)d_in[7];
    const float* bih1 = (const float*)d_in[8];
    const float* bhh1 = (const float*)d_in[9];
    const float* w1   = (const float*)d_in[10];
    const float* b1   = (const float*)d_in[11];
    const float* w2   = (const float*)d_in[12];
    const float* b2   = (const float*)d_in[13];

    float* xp_p = nullptr;
    __nv_bfloat16 *a3_p = nullptr, *w3_p = nullptr;
    cudaGetSymbolAddress((void**)&xp_p, g_xp);
    cudaGetSymbolAddress((void**)&a3_p, g_a3);
    cudaGetSymbolAddress((void**)&w3_p, g_w3);

    const size_t sm_tc = (size_t)(2 * 48 * PW + 32 * PA) * sizeof(__nv_bfloat16)
                       + (size_t)(128 * 13) * sizeof(float);
    cudaFuncSetAttribute(recur_tc_kernel, cudaFuncAttributeMaxDynamicSharedMemorySize, (int)sm_tc);
    const size_t sm_gemm = (size_t)6 * 128 * PKH * sizeof(__nv_bfloat16);
    cudaFuncSetAttribute(bgemm_kernel, cudaFuncAttributeMaxDynamicSharedMemorySize, (int)sm_gemm);

    // ---- layer 0 ----
    init_kernel<<<64, 256>>>();
    embed_split_kernel<<<MM, 160>>>(x, emb);
    {
        const long pw = (long)(2 * GG) * (320 / 2);
        conv_split_kernel<<<(unsigned)((pw + 255) / 256), 256>>>(wih0, w3_p, 2 * GG, EE, 320, 1);
    }
    bgemm_kernel<<<dim3(GG / 128, MM / 128, 2), 256, sm_gemm>>>(a3_p, w3_p, bih0, xp_p, MM, GG, 960);
    // W split for layer 1
    {
        const long pw = (long)(2 * GG) * (1024 / 2);
        conv_split_kernel<<<(unsigned)((pw + 255) / 256), 256>>>(wih1, w3_p, 2 * GG, 2 * HH, 1024, 1);
    }
    recur_tc_kernel<<<128, 256, sm_tc>>>(xp_p, whh0, bhh0, a3_p, 0);  // writes layer-1 split A

    // ---- layer 1 ----
    bgemm_kernel<<<dim3(GG / 128, MM / 128, 2), 256, sm_gemm>>>(a3_p, w3_p, bih1, xp_p, MM, GG, 3072);
    init_kernel<<<64, 256>>>();
    recur_tc_kernel<<<128, 256, sm_tc>>>(xp_p, whh1, bhh1, nullptr, 1);

    // ---- head ----
    mlp1_kernel<<<(BB * 128 * 32) / 256, 256>>>(w1, b1);
    mlp2_kernel<<<1, 128>>>(w2, b2, (float*)d_out);
}